// round 1
// baseline (speedup 1.0000x reference)
#include <cuda_runtime.h>
#include <math.h>

#define BB   4
#define QQ   512
#define KKT  1024
#define DD   512
#define HH   8
#define DH   64
#define DFF  2048
#define NL   12
#define NV   332
#define MEML 512

// ---------------- scratch (static device globals; no allocation) ----------------
__device__ float g_h[BB*QQ*DD];          // residual stream
__device__ float g_norm[BB*QQ*DD];       // layernorm output
__device__ float g_wh[BB*QQ*3*DD];       // qkv projections of the Q rows
__device__ float g_whmem[3*DD];          // qkv projection of the (constant) mem row
__device__ float g_posemb[KKT*DD];
__device__ float g_rk[KKT*DD];
__device__ float g_qw[BB*HH*QQ*DH];      // q + r_w_bias, head-major
__device__ float g_qr[BB*HH*QQ*DH];      // q + r_r_bias, head-major
__device__ float g_kt[BB*HH*KKT*DH];     // K, [bh][j][d]
__device__ float g_vtd[BB*HH*DH*KKT];    // V, [bh][d][j]  (d-major for PV gemm)
__device__ float g_rkt[HH*KKT*DH];       // rk, [h][u][d]
__device__ float g_ac[(long)BB*HH*QQ*KKT];   // content scores -> probs
__device__ float g_bd[(long)BB*HH*QQ*KKT];   // position scores (unshifted index u)
__device__ float g_attn[BB*QQ*DD];
__device__ float g_ff[BB*QQ*DFF];
__device__ float g_gath[BB*QQ*DD];
__device__ float g_sums[BB*HH*QQ];

// ---------------- generic tiled SGEMM: C = alpha*A@B^T (+bias)(relu)(+add) ----------------
// A: [M,Kd] row-major, B: [N,Kd] row-major, C: row stride ldc.
// batch z: off = (z/zdiv)*sHi + (z%zdiv)*sLo per operand.
__global__ void gemm64(const float* __restrict__ A, const float* __restrict__ B,
                       float* __restrict__ C,
                       int M, int N, int Kd, int ldc,
                       int zdA, long long hA, long long lA,
                       int zdB, long long hB, long long lB,
                       int zdC, long long hC, long long lC,
                       const float* __restrict__ addsrc, int ldadd,
                       const float* __restrict__ bias,
                       float alpha, int relu)
{
    __shared__ float As[16][64];
    __shared__ float Bs[16][64];
    int z = blockIdx.z;
    A += (long long)(z / zdA) * hA + (long long)(z % zdA) * lA;
    B += (long long)(z / zdB) * hB + (long long)(z % zdB) * lB;
    C += (long long)(z / zdC) * hC + (long long)(z % zdC) * lC;
    int bm = blockIdx.y * 64, bn = blockIdx.x * 64;
    int tid = threadIdx.x;
    int tx = tid & 15, ty = tid >> 4;
    float acc[4][4];
#pragma unroll
    for (int i = 0; i < 4; i++)
#pragma unroll
        for (int j = 0; j < 4; j++) acc[i][j] = 0.f;

    for (int k0 = 0; k0 < Kd; k0 += 16) {
#pragma unroll
        for (int t = 0; t < 4; t++) {
            int e = tid + t * 256;
            int m = e >> 4, kk = e & 15;
            int gm = bm + m;
            As[kk][m] = (gm < M) ? A[(long long)gm * Kd + k0 + kk] : 0.f;
            int gn = bn + m;
            Bs[kk][m] = (gn < N) ? B[(long long)gn * Kd + k0 + kk] : 0.f;
        }
        __syncthreads();
#pragma unroll
        for (int kk = 0; kk < 16; kk++) {
            float a[4], b[4];
#pragma unroll
            for (int i = 0; i < 4; i++) a[i] = As[kk][ty + 16 * i];
#pragma unroll
            for (int j = 0; j < 4; j++) b[j] = Bs[kk][tx + 16 * j];
#pragma unroll
            for (int i = 0; i < 4; i++)
#pragma unroll
                for (int j = 0; j < 4; j++)
                    acc[i][j] += a[i] * b[j];
        }
        __syncthreads();
    }
#pragma unroll
    for (int i = 0; i < 4; i++) {
        int gm = bm + ty + 16 * i;
        if (gm >= M) continue;
#pragma unroll
        for (int j = 0; j < 4; j++) {
            int gn = bn + tx + 16 * j;
            if (gn >= N) continue;
            float v = alpha * acc[i][j];
            if (bias) v += bias[gn];
            if (relu) v = fmaxf(v, 0.f);
            if (addsrc) v += addsrc[(long long)gm * ldadd + gn];
            C[(long long)gm * ldc + gn] = v;
        }
    }
}

// ---------------- layernorm over 512-wide rows ----------------
__global__ void ln_kernel(const float* __restrict__ x, float* __restrict__ y,
                          const float* __restrict__ g, const float* __restrict__ b)
{
    int row = blockIdx.x;
    const float* xr = x + (long long)row * DD;
    float* yr = y + (long long)row * DD;
    int tid = threadIdx.x;  // 256
    float v0 = xr[tid], v1 = xr[tid + 256];
    float s = v0 + v1, s2 = v0 * v0 + v1 * v1;
    __shared__ float sh[16];
#pragma unroll
    for (int o = 16; o > 0; o >>= 1) {
        s  += __shfl_xor_sync(0xffffffffu, s,  o);
        s2 += __shfl_xor_sync(0xffffffffu, s2, o);
    }
    if ((tid & 31) == 0) { sh[tid >> 5] = s; sh[(tid >> 5) + 8] = s2; }
    __syncthreads();
    __shared__ float mu_s, rs_s;
    if (tid == 0) {
        float S = 0.f, S2 = 0.f;
        for (int w = 0; w < 8; w++) { S += sh[w]; S2 += sh[w + 8]; }
        float mu = S / DD;
        float var = S2 / DD - mu * mu;
        mu_s = mu;
        rs_s = rsqrtf(var + 1e-3f);
    }
    __syncthreads();
    float mu = mu_s, rs = rs_s;
    yr[tid]       = (v0 - mu) * rs * g[tid]       + b[tid];
    yr[tid + 256] = (v1 - mu) * rs * g[tid + 256] + b[tid + 256];
}

// wh_mem[n] = sum_c ln1_b[c] * qkv_w[n,c]   (LN of a zero row == bias vector)
__global__ void whmem_kernel(const float* __restrict__ qkvw, const float* __restrict__ lnb)
{
    int n = blockIdx.x * blockDim.x + threadIdx.x;
    if (n >= 3 * DD) return;
    const float* wr = qkvw + (long long)n * DD;
    float s = 0.f;
    for (int c = 0; c < DD; c++) s += lnb[c] * wr[c];
    g_whmem[n] = s;
}

__global__ void posemb_kernel()
{
    int idx = blockIdx.x * blockDim.x + threadIdx.x;
    if (idx >= KKT * DD) return;
    int p = idx / DD, c = idx % DD;
    float pos = (float)(KKT - 1 - p);
    int k = (c < 256) ? c : (c - 256);
    float invf = powf(10000.0f, -((float)(2 * k)) / 512.0f);
    float a = pos * invf;
    g_posemb[idx] = (c < 256) ? sinf(a) : cosf(a);
}

__global__ void gather_kernel(const int* __restrict__ ids, const float* __restrict__ emb)
{
    int idx = blockIdx.x * blockDim.x + threadIdx.x;
    if (idx >= BB * QQ * DD) return;
    int m = idx / DD, c = idx % DD;
    g_gath[idx] = emb[(long long)ids[m] * DD + c];
}

__global__ void packq_kernel(const float* __restrict__ rwb, const float* __restrict__ rrb)
{
    int idx = blockIdx.x * blockDim.x + threadIdx.x;
    if (idx >= BB * QQ * DD) return;
    int bq = idx / DD, c = idx % DD;
    int h = c >> 6, d = c & 63;
    int b = bq / QQ, i = bq % QQ;
    float qv = g_wh[(long long)bq * (3 * DD) + c];
    long long o = (((long long)(b * HH + h)) * QQ + i) * DH + d;
    g_qw[o] = qv + rwb[c];
    g_qr[o] = qv + rrb[c];
}

__global__ void packkv_kernel()
{
    int idx = blockIdx.x * blockDim.x + threadIdx.x;
    if (idx >= BB * HH * KKT * DH) return;
    int d = idx & 63;
    int j = (idx >> 6) & 1023;
    int bh = idx >> 16;
    int b = bh >> 3, h = bh & 7;
    int c = h * 64 + d;
    float kv, vv;
    if (j < MEML) {
        kv = g_whmem[DD + c];
        vv = g_whmem[2 * DD + c];
    } else {
        long long r = (long long)(b * QQ + (j - MEML)) * (3 * DD);
        kv = g_wh[r + DD + c];
        vv = g_wh[r + 2 * DD + c];
    }
    g_kt[idx] = kv;
    g_vtd[((long long)bh * DH + d) * KKT + j] = vv;
}

__global__ void packrk_kernel()
{
    int idx = blockIdx.x * blockDim.x + threadIdx.x;
    if (idx >= HH * KKT * DH) return;
    int d = idx & 63;
    int p = (idx >> 6) & 1023;
    int h = idx >> 16;
    g_rkt[idx] = g_rk[(long long)p * DD + h * 64 + d];
}

// softmax over key axis with rel_shift index remap; probs (unnormalized) back into g_ac,
// row sums to g_sums (normalization folded in after PV).
__global__ void softmax_kernel()
{
    long long blk = blockIdx.x;              // blk = bh*QQ + i
    int i = (int)(blk % QQ);
    float* ac = g_ac + blk * KKT;
    const float* bd = g_bd + blk * KKT;
    int jmax = i + MEML;                     // inclusive; j > jmax is masked
    int tid = threadIdx.x;                   // 256
    float mx = -3.0e38f;
    for (int j = tid; j <= jmax; j += 256) {
        float s = 0.125f * (ac[j] + bd[j - i + (QQ - 1)]);
        ac[j] = s;
        mx = fmaxf(mx, s);
    }
    __shared__ float sh[8];
#pragma unroll
    for (int o = 16; o > 0; o >>= 1) mx = fmaxf(mx, __shfl_xor_sync(0xffffffffu, mx, o));
    if ((tid & 31) == 0) sh[tid >> 5] = mx;
    __syncthreads();
    if (tid == 0) {
        float m = sh[0];
        for (int w = 1; w < 8; w++) m = fmaxf(m, sh[w]);
        sh[0] = m;
    }
    __syncthreads();
    mx = sh[0];
    __syncthreads();
    float sum = 0.f;
    for (int j = tid; j < KKT; j += 256) {
        float e = (j <= jmax) ? expf(ac[j] - mx) : 0.f;
        ac[j] = e;
        sum += e;
    }
#pragma unroll
    for (int o = 16; o > 0; o >>= 1) sum += __shfl_xor_sync(0xffffffffu, sum, o);
    if ((tid & 31) == 0) sh[tid >> 5] = sum;
    __syncthreads();
    if (tid == 0) {
        float s = 0.f;
        for (int w = 0; w < 8; w++) s += sh[w];
        g_sums[blk] = s;
    }
}

__global__ void norm_attn_kernel()
{
    int idx = blockIdx.x * blockDim.x + threadIdx.x;
    if (idx >= BB * QQ * DD) return;
    int bq = idx / DD, c = idx % DD;
    int b = bq / QQ, i = bq % QQ, h = c >> 6;
    g_attn[idx] /= g_sums[(long long)(b * HH + h) * QQ + i];
}

// ---------------- host ----------------
static void gemm(const float* A, const float* B, float* C,
                 int M, int N, int K, int ldc, int nz,
                 int zdA, long long hA, long long lA,
                 int zdB, long long hB, long long lB,
                 int zdC, long long hC, long long lC,
                 const float* add, int ldadd, const float* bias,
                 float alpha, int relu)
{
    dim3 grid((N + 63) / 64, (M + 63) / 64, nz);
    gemm64<<<grid, 256>>>(A, B, C, M, N, K, ldc,
                          zdA, hA, lA, zdB, hB, lB, zdC, hC, lC,
                          add, ldadd, bias, alpha, relu);
}

extern "C" void kernel_launch(void* const* d_in, const int* in_sizes, int n_in,
                              void* d_out, int out_size)
{
    const int*   ids      = (const int*)d_in[0];
    const float* emb      = (const float*)d_in[1];
    const float* emb_proj = (const float*)d_in[2];
    const float* rwb      = (const float*)d_in[3];
    const float* rrb      = (const float*)d_in[4];
    const float* qkv_w    = (const float*)d_in[5];
    const float* o_w      = (const float*)d_in[6];
    const float* rnet_w   = (const float*)d_in[7];
    const float* ln1g     = (const float*)d_in[8];
    const float* ln1b     = (const float*)d_in[9];
    const float* ff1w     = (const float*)d_in[10];
    const float* ff1b     = (const float*)d_in[11];
    const float* ff2w     = (const float*)d_in[12];
    const float* ff2b     = (const float*)d_in[13];
    const float* ln2g     = (const float*)d_in[14];
    const float* ln2b     = (const float*)d_in[15];
    const float* headw    = (const float*)d_in[16];
    const float* headb    = (const float*)d_in[17];
    float* out = (float*)d_out;

    float *p_h, *p_norm, *p_wh, *p_posemb, *p_rk, *p_qw, *p_qr, *p_kt, *p_vtd,
          *p_rkt, *p_ac, *p_bd, *p_attn, *p_ff, *p_gath;
    void* tmp;
#define SYM(v, s) cudaGetSymbolAddress(&tmp, s); v = (float*)tmp;
    SYM(p_h, g_h) SYM(p_norm, g_norm) SYM(p_wh, g_wh) SYM(p_posemb, g_posemb)
    SYM(p_rk, g_rk) SYM(p_qw, g_qw) SYM(p_qr, g_qr) SYM(p_kt, g_kt)
    SYM(p_vtd, g_vtd) SYM(p_rkt, g_rkt) SYM(p_ac, g_ac) SYM(p_bd, g_bd)
    SYM(p_attn, g_attn) SYM(p_ff, g_ff) SYM(p_gath, g_gath)
#undef SYM

    const int MQ = BB * QQ;  // 2048 token rows

    // ---- setup: embedding + positional ----
    gather_kernel<<<(MQ * DD + 255) / 256, 256>>>(ids, emb);
    posemb_kernel<<<(KKT * DD + 255) / 256, 256>>>();
    gemm(p_gath, emb_proj, p_h, MQ, DD, DD, DD, 1,
         1, 0, 0, 1, 0, 0, 1, 0, 0, nullptr, 0, nullptr, sqrtf((float)DD), 0);

    for (int l = 0; l < NL; l++) {
        const float* qkvw_l = qkv_w + (long long)l * 3 * DD * DD;
        const float* ow_l   = o_w   + (long long)l * DD * DD;
        const float* rnw_l  = rnet_w+ (long long)l * DD * DD;
        const float* f1w_l  = ff1w  + (long long)l * DFF * DD;
        const float* f1b_l  = ff1b  + (long long)l * DFF;
        const float* f2w_l  = ff2w  + (long long)l * DD * DFF;
        const float* f2b_l  = ff2b  + (long long)l * DD;

        // LN1 + QKV
        ln_kernel<<<MQ, 256>>>(p_h, p_norm, ln1g + l * DD, ln1b + l * DD);
        whmem_kernel<<<12, 128>>>(qkvw_l, ln1b + l * DD);
        gemm(p_norm, qkvw_l, p_wh, MQ, 3 * DD, DD, 3 * DD, 1,
             1, 0, 0, 1, 0, 0, 1, 0, 0, nullptr, 0, nullptr, 1.f, 0);

        // rk = pos_emb @ r_net_w^T
        gemm(p_posemb, rnw_l, p_rk, KKT, DD, DD, DD, 1,
             1, 0, 0, 1, 0, 0, 1, 0, 0, nullptr, 0, nullptr, 1.f, 0);

        // repack for attention
        packq_kernel<<<(MQ * DD + 255) / 256, 256>>>(rwb, rrb);
        packkv_kernel<<<(BB * HH * KKT * DH + 255) / 256, 256>>>();
        packrk_kernel<<<(HH * KKT * DH + 255) / 256, 256>>>();

        // AC[z] = Qw[z] @ K[z]^T     (z = b*8+h, 32 batches)
        gemm(p_qw, p_kt, p_ac, QQ, KKT, DH, KKT, BB * HH,
             1, (long long)QQ * DH, 0,
             1, (long long)KKT * DH, 0,
             1, (long long)QQ * KKT, 0, nullptr, 0, nullptr, 1.f, 0);
        // BDu[z] = Qr[z] @ rk[h]^T   (B operand indexed by z%8)
        gemm(p_qr, p_rkt, p_bd, QQ, KKT, DH, KKT, BB * HH,
             1, (long long)QQ * DH, 0,
             8, 0, (long long)KKT * DH,
             1, (long long)QQ * KKT, 0, nullptr, 0, nullptr, 1.f, 0);

        softmax_kernel<<<BB * HH * QQ, 256>>>();

        // attn[z] = P[z] @ V[z]  -> scattered into [b, i, h*64+d]
        gemm(p_ac, p_vtd, p_attn, QQ, DH, KKT, DD, BB * HH,
             1, (long long)QQ * KKT, 0,
             1, (long long)DH * KKT, 0,
             8, (long long)QQ * DD, 64, nullptr, 0, nullptr, 1.f, 0);
        norm_attn_kernel<<<(MQ * DD + 255) / 256, 256>>>();

        // O projection + residual
        gemm(p_attn, ow_l, p_h, MQ, DD, DD, DD, 1,
             1, 0, 0, 1, 0, 0, 1, 0, 0, p_h, DD, nullptr, 1.f, 0);

        // FFN
        ln_kernel<<<MQ, 256>>>(p_h, p_norm, ln2g + l * DD, ln2b + l * DD);
        gemm(p_norm, f1w_l, p_ff, MQ, DFF, DD, DFF, 1,
             1, 0, 0, 1, 0, 0, 1, 0, 0, nullptr, 0, f1b_l, 1.f, 1);
        gemm(p_ff, f2w_l, p_h, MQ, DD, DFF, DD, 1,
             1, 0, 0, 1, 0, 0, 1, 0, 0, p_h, DD, f2b_l, 1.f, 0);
    }

    // vocab head
    gemm(p_h, headw, out, MQ, NV, DD, NV, 1,
         1, 0, 0, 1, 0, 0, 1, 0, 0, nullptr, 0, headb, 1.f, 0);
}

// round 2
// speedup vs baseline: 1.3645x; 1.3645x over previous
#include <cuda_runtime.h>
#include <math.h>

#define BB   4
#define QQ   512
#define KKT  1024
#define DD   512
#define HH   8
#define DH   64
#define DFF  2048
#define NL   12
#define NV   332
#define MEML 512

// ---------------- scratch (static device globals; no allocation) ----------------
__device__ float g_h[BB*QQ*DD];
__device__ float g_norm[BB*QQ*DD];
__device__ float g_wh[BB*QQ*3*DD];
__device__ float g_whmem[3*DD];
__device__ float g_posemb[KKT*DD];
__device__ float g_rk[KKT*DD];
__device__ float g_qw[BB*HH*QQ*DH];
__device__ float g_qr[BB*HH*QQ*DH];
__device__ float g_kt[BB*HH*KKT*DH];
__device__ float g_vtd[BB*HH*DH*KKT];
__device__ float g_rkt[HH*KKT*DH];
__device__ float g_ac[(long)BB*HH*QQ*KKT];
__device__ float g_bd[(long)BB*HH*QQ*KKT];
__device__ float g_attn[BB*QQ*DD];
__device__ float g_ff[BB*QQ*DFF];
__device__ float g_gath[BB*QQ*DD];
__device__ float g_sums[BB*HH*QQ];

// ---------------- 128x128 double-buffered SGEMM: C = alpha*A@B^T (+bias)(relu)(+add) ----
// A: [M,Kd] row-major, B: [N,Kd] row-major. Kd must be a multiple of 16 and
// A/B rows 16B-aligned (true for all call sites). M multiple of 128 helps but
// guards cover everything.
#define BM 128
#define BN 128
#define LDA 132   // +4 pad: keeps float4 alignment, limits STS conflicts to 2-way

__global__ __launch_bounds__(256, 2)
void gemm128(const float* __restrict__ A, const float* __restrict__ B,
             float* __restrict__ C,
             int M, int N, int Kd, int ldc,
             int zdA, long long hA, long long lA,
             int zdB, long long hB, long long lB,
             int zdC, long long hC, long long lC,
             const float* __restrict__ addsrc, int ldadd,
             const float* __restrict__ bias,
             float alpha, int relu)
{
    __shared__ float As[2][16][LDA];
    __shared__ float Bs[2][16][LDA];

    int z = blockIdx.z;
    A += (long long)(z / zdA) * hA + (long long)(z % zdA) * lA;
    B += (long long)(z / zdB) * hB + (long long)(z % zdB) * lB;
    C += (long long)(z / zdC) * hC + (long long)(z % zdC) * lC;

    int bm = blockIdx.y * BM, bn = blockIdx.x * BN;
    int tid = threadIdx.x;
    int tx = tid & 15, ty = tid >> 4;

    // global->reg staging indices: 512 float4 per operand tile, 2 per thread
    int lrow = tid >> 2;             // 0..63  (+64 on second trip)
    int lkq  = (tid & 3) * 4;        // 0,4,8,12

    float acc[8][8];
#pragma unroll
    for (int i = 0; i < 8; i++)
#pragma unroll
        for (int j = 0; j < 8; j++) acc[i][j] = 0.f;

    float4 pa[2], pb[2];

    auto ldgA = [&](int k0, int it) -> float4 {
        int gm = bm + lrow + it * 64;
        if (gm < M) return *(const float4*)&A[(long long)gm * Kd + k0 + lkq];
        return make_float4(0.f, 0.f, 0.f, 0.f);
    };
    auto ldgB = [&](int k0, int it) -> float4 {
        int gn = bn + lrow + it * 64;
        if (gn < N) return *(const float4*)&B[(long long)gn * Kd + k0 + lkq];
        return make_float4(0.f, 0.f, 0.f, 0.f);
    };
    auto stash = [&](int buf) {
#pragma unroll
        for (int it = 0; it < 2; it++) {
            int r = lrow + it * 64;
            As[buf][lkq + 0][r] = pa[it].x;
            As[buf][lkq + 1][r] = pa[it].y;
            As[buf][lkq + 2][r] = pa[it].z;
            As[buf][lkq + 3][r] = pa[it].w;
            Bs[buf][lkq + 0][r] = pb[it].x;
            Bs[buf][lkq + 1][r] = pb[it].y;
            Bs[buf][lkq + 2][r] = pb[it].z;
            Bs[buf][lkq + 3][r] = pb[it].w;
        }
    };

    int nk = Kd >> 4;
    pa[0] = ldgA(0, 0); pa[1] = ldgA(0, 1);
    pb[0] = ldgB(0, 0); pb[1] = ldgB(0, 1);
    stash(0);
    __syncthreads();

    int buf = 0;
    for (int t = 0; t < nk; t++) {
        int has_next = (t + 1 < nk);
        if (has_next) {
            int k0 = (t + 1) << 4;
            pa[0] = ldgA(k0, 0); pa[1] = ldgA(k0, 1);
            pb[0] = ldgB(k0, 0); pb[1] = ldgB(k0, 1);
        }
#pragma unroll
        for (int kk = 0; kk < 16; kk++) {
            float4 a0 = *(const float4*)&As[buf][kk][ty * 4];
            float4 a1 = *(const float4*)&As[buf][kk][ty * 4 + 64];
            float4 b0 = *(const float4*)&Bs[buf][kk][tx * 4];
            float4 b1 = *(const float4*)&Bs[buf][kk][tx * 4 + 64];
            float av[8] = {a0.x, a0.y, a0.z, a0.w, a1.x, a1.y, a1.z, a1.w};
            float bv[8] = {b0.x, b0.y, b0.z, b0.w, b1.x, b1.y, b1.z, b1.w};
#pragma unroll
            for (int i = 0; i < 8; i++)
#pragma unroll
                for (int j = 0; j < 8; j++)
                    acc[i][j] += av[i] * bv[j];
        }
        if (has_next) {
            stash(buf ^ 1);
            __syncthreads();
            buf ^= 1;
        }
    }

#pragma unroll
    for (int i = 0; i < 8; i++) {
        int gm = bm + ((i < 4) ? (ty * 4 + i) : (64 + ty * 4 + i - 4));
        if (gm >= M) continue;
#pragma unroll
        for (int j = 0; j < 8; j++) {
            int gn = bn + ((j < 4) ? (tx * 4 + j) : (64 + tx * 4 + j - 4));
            if (gn >= N) continue;
            float v = alpha * acc[i][j];
            if (bias) v += bias[gn];
            if (relu) v = fmaxf(v, 0.f);
            if (addsrc) v += addsrc[(long long)gm * ldadd + gn];
            C[(long long)gm * ldc + gn] = v;
        }
    }
}

// ---------------- layernorm over 512-wide rows ----------------
__global__ void ln_kernel(const float* __restrict__ x, float* __restrict__ y,
                          const float* __restrict__ g, const float* __restrict__ b)
{
    int row = blockIdx.x;
    const float* xr = x + (long long)row * DD;
    float* yr = y + (long long)row * DD;
    int tid = threadIdx.x;  // 256
    float v0 = xr[tid], v1 = xr[tid + 256];
    float s = v0 + v1, s2 = v0 * v0 + v1 * v1;
    __shared__ float sh[16];
#pragma unroll
    for (int o = 16; o > 0; o >>= 1) {
        s  += __shfl_xor_sync(0xffffffffu, s,  o);
        s2 += __shfl_xor_sync(0xffffffffu, s2, o);
    }
    if ((tid & 31) == 0) { sh[tid >> 5] = s; sh[(tid >> 5) + 8] = s2; }
    __syncthreads();
    __shared__ float mu_s, rs_s;
    if (tid == 0) {
        float S = 0.f, S2 = 0.f;
        for (int w = 0; w < 8; w++) { S += sh[w]; S2 += sh[w + 8]; }
        float mu = S / DD;
        float var = S2 / DD - mu * mu;
        mu_s = mu;
        rs_s = rsqrtf(var + 1e-3f);
    }
    __syncthreads();
    float mu = mu_s, rs = rs_s;
    yr[tid]       = (v0 - mu) * rs * g[tid]       + b[tid];
    yr[tid + 256] = (v1 - mu) * rs * g[tid + 256] + b[tid + 256];
}

__global__ void whmem_kernel(const float* __restrict__ qkvw, const float* __restrict__ lnb)
{
    int n = blockIdx.x * blockDim.x + threadIdx.x;
    if (n >= 3 * DD) return;
    const float* wr = qkvw + (long long)n * DD;
    float s = 0.f;
    for (int c = 0; c < DD; c++) s += lnb[c] * wr[c];
    g_whmem[n] = s;
}

__global__ void posemb_kernel()
{
    int idx = blockIdx.x * blockDim.x + threadIdx.x;
    if (idx >= KKT * DD) return;
    int p = idx / DD, c = idx % DD;
    float pos = (float)(KKT - 1 - p);
    int k = (c < 256) ? c : (c - 256);
    float invf = powf(10000.0f, -((float)(2 * k)) / 512.0f);
    float a = pos * invf;
    g_posemb[idx] = (c < 256) ? sinf(a) : cosf(a);
}

__global__ void gather_kernel(const int* __restrict__ ids, const float* __restrict__ emb)
{
    int idx = blockIdx.x * blockDim.x + threadIdx.x;
    if (idx >= BB * QQ * DD) return;
    int m = idx / DD, c = idx % DD;
    g_gath[idx] = emb[(long long)ids[m] * DD + c];
}

__global__ void packq_kernel(const float* __restrict__ rwb, const float* __restrict__ rrb)
{
    int idx = blockIdx.x * blockDim.x + threadIdx.x;
    if (idx >= BB * QQ * DD) return;
    int bq = idx / DD, c = idx % DD;
    int h = c >> 6, d = c & 63;
    int b = bq / QQ, i = bq % QQ;
    float qv = g_wh[(long long)bq * (3 * DD) + c];
    long long o = (((long long)(b * HH + h)) * QQ + i) * DH + d;
    g_qw[o] = qv + rwb[c];
    g_qr[o] = qv + rrb[c];
}

__global__ void packkv_kernel()
{
    int idx = blockIdx.x * blockDim.x + threadIdx.x;
    if (idx >= BB * HH * KKT * DH) return;
    int d = idx & 63;
    int j = (idx >> 6) & 1023;
    int bh = idx >> 16;
    int b = bh >> 3, h = bh & 7;
    int c = h * 64 + d;
    float kv, vv;
    if (j < MEML) {
        kv = g_whmem[DD + c];
        vv = g_whmem[2 * DD + c];
    } else {
        long long r = (long long)(b * QQ + (j - MEML)) * (3 * DD);
        kv = g_wh[r + DD + c];
        vv = g_wh[r + 2 * DD + c];
    }
    g_kt[idx] = kv;
    g_vtd[((long long)bh * DH + d) * KKT + j] = vv;
}

__global__ void packrk_kernel()
{
    int idx = blockIdx.x * blockDim.x + threadIdx.x;
    if (idx >= HH * KKT * DH) return;
    int d = idx & 63;
    int p = (idx >> 6) & 1023;
    int h = idx >> 16;
    g_rkt[idx] = g_rk[(long long)p * DD + h * 64 + d];
}

__global__ void softmax_kernel()
{
    long long blk = blockIdx.x;              // blk = bh*QQ + i
    int i = (int)(blk % QQ);
    float* ac = g_ac + blk * KKT;
    const float* bd = g_bd + blk * KKT;
    int jmax = i + MEML;
    int tid = threadIdx.x;                   // 256
    float mx = -3.0e38f;
    for (int j = tid; j <= jmax; j += 256) {
        float s = 0.125f * (ac[j] + bd[j - i + (QQ - 1)]);
        ac[j] = s;
        mx = fmaxf(mx, s);
    }
    __shared__ float sh[8];
#pragma unroll
    for (int o = 16; o > 0; o >>= 1) mx = fmaxf(mx, __shfl_xor_sync(0xffffffffu, mx, o));
    if ((tid & 31) == 0) sh[tid >> 5] = mx;
    __syncthreads();
    if (tid == 0) {
        float m = sh[0];
        for (int w = 1; w < 8; w++) m = fmaxf(m, sh[w]);
        sh[0] = m;
    }
    __syncthreads();
    mx = sh[0];
    __syncthreads();
    float sum = 0.f;
    for (int j = tid; j < KKT; j += 256) {
        float e = (j <= jmax) ? expf(ac[j] - mx) : 0.f;
        ac[j] = e;
        sum += e;
    }
#pragma unroll
    for (int o = 16; o > 0; o >>= 1) sum += __shfl_xor_sync(0xffffffffu, sum, o);
    if ((tid & 31) == 0) sh[tid >> 5] = sum;
    __syncthreads();
    if (tid == 0) {
        float s = 0.f;
        for (int w = 0; w < 8; w++) s += sh[w];
        g_sums[blk] = s;
    }
}

__global__ void norm_attn_kernel()
{
    int idx = blockIdx.x * blockDim.x + threadIdx.x;
    if (idx >= BB * QQ * DD) return;
    int bq = idx / DD, c = idx % DD;
    int b = bq / QQ, i = bq % QQ, h = c >> 6;
    g_attn[idx] /= g_sums[(long long)(b * HH + h) * QQ + i];
}

// ---------------- host ----------------
static void gemm(const float* A, const float* B, float* C,
                 int M, int N, int K, int ldc, int nz,
                 int zdA, long long hA, long long lA,
                 int zdB, long long hB, long long lB,
                 int zdC, long long hC, long long lC,
                 const float* add, int ldadd, const float* bias,
                 float alpha, int relu)
{
    dim3 grid((N + BN - 1) / BN, (M + BM - 1) / BM, nz);
    gemm128<<<grid, 256>>>(A, B, C, M, N, K, ldc,
                           zdA, hA, lA, zdB, hB, lB, zdC, hC, lC,
                           add, ldadd, bias, alpha, relu);
}

extern "C" void kernel_launch(void* const* d_in, const int* in_sizes, int n_in,
                              void* d_out, int out_size)
{
    const int*   ids      = (const int*)d_in[0];
    const float* emb      = (const float*)d_in[1];
    const float* emb_proj = (const float*)d_in[2];
    const float* rwb      = (const float*)d_in[3];
    const float* rrb      = (const float*)d_in[4];
    const float* qkv_w    = (const float*)d_in[5];
    const float* o_w      = (const float*)d_in[6];
    const float* rnet_w   = (const float*)d_in[7];
    const float* ln1g     = (const float*)d_in[8];
    const float* ln1b     = (const float*)d_in[9];
    const float* ff1w     = (const float*)d_in[10];
    const float* ff1b     = (const float*)d_in[11];
    const float* ff2w     = (const float*)d_in[12];
    const float* ff2b     = (const float*)d_in[13];
    const float* ln2g     = (const float*)d_in[14];
    const float* ln2b     = (const float*)d_in[15];
    const float* headw    = (const float*)d_in[16];
    const float* headb    = (const float*)d_in[17];
    float* out = (float*)d_out;

    float *p_h, *p_norm, *p_wh, *p_posemb, *p_rk, *p_qw, *p_qr, *p_kt, *p_vtd,
          *p_rkt, *p_ac, *p_bd, *p_attn, *p_ff, *p_gath;
    void* tmp;
#define SYM(v, s) cudaGetSymbolAddress(&tmp, s); v = (float*)tmp;
    SYM(p_h, g_h) SYM(p_norm, g_norm) SYM(p_wh, g_wh) SYM(p_posemb, g_posemb)
    SYM(p_rk, g_rk) SYM(p_qw, g_qw) SYM(p_qr, g_qr) SYM(p_kt, g_kt)
    SYM(p_vtd, g_vtd) SYM(p_rkt, g_rkt) SYM(p_ac, g_ac) SYM(p_bd, g_bd)
    SYM(p_attn, g_attn) SYM(p_ff, g_ff) SYM(p_gath, g_gath)
#undef SYM

    const int MQ = BB * QQ;  // 2048 token rows

    gather_kernel<<<(MQ * DD + 255) / 256, 256>>>(ids, emb);
    posemb_kernel<<<(KKT * DD + 255) / 256, 256>>>();
    gemm(p_gath, emb_proj, p_h, MQ, DD, DD, DD, 1,
         1, 0, 0, 1, 0, 0, 1, 0, 0, nullptr, 0, nullptr, sqrtf((float)DD), 0);

    for (int l = 0; l < NL; l++) {
        const float* qkvw_l = qkv_w + (long long)l * 3 * DD * DD;
        const float* ow_l   = o_w   + (long long)l * DD * DD;
        const float* rnw_l  = rnet_w+ (long long)l * DD * DD;
        const float* f1w_l  = ff1w  + (long long)l * DFF * DD;
        const float* f1b_l  = ff1b  + (long long)l * DFF;
        const float* f2w_l  = ff2w  + (long long)l * DD * DFF;
        const float* f2b_l  = ff2b  + (long long)l * DD;

        ln_kernel<<<MQ, 256>>>(p_h, p_norm, ln1g + l * DD, ln1b + l * DD);
        whmem_kernel<<<12, 128>>>(qkvw_l, ln1b + l * DD);
        gemm(p_norm, qkvw_l, p_wh, MQ, 3 * DD, DD, 3 * DD, 1,
             1, 0, 0, 1, 0, 0, 1, 0, 0, nullptr, 0, nullptr, 1.f, 0);

        gemm(p_posemb, rnw_l, p_rk, KKT, DD, DD, DD, 1,
             1, 0, 0, 1, 0, 0, 1, 0, 0, nullptr, 0, nullptr, 1.f, 0);

        packq_kernel<<<(MQ * DD + 255) / 256, 256>>>(rwb, rrb);
        packkv_kernel<<<(BB * HH * KKT * DH + 255) / 256, 256>>>();
        packrk_kernel<<<(HH * KKT * DH + 255) / 256, 256>>>();

        gemm(p_qw, p_kt, p_ac, QQ, KKT, DH, KKT, BB * HH,
             1, (long long)QQ * DH, 0,
             1, (long long)KKT * DH, 0,
             1, (long long)QQ * KKT, 0, nullptr, 0, nullptr, 1.f, 0);
        gemm(p_qr, p_rkt, p_bd, QQ, KKT, DH, KKT, BB * HH,
             1, (long long)QQ * DH, 0,
             8, 0, (long long)KKT * DH,
             1, (long long)QQ * KKT, 0, nullptr, 0, nullptr, 1.f, 0);

        softmax_kernel<<<BB * HH * QQ, 256>>>();

        gemm(p_ac, p_vtd, p_attn, QQ, DH, KKT, DD, BB * HH,
             1, (long long)QQ * KKT, 0,
             1, (long long)DH * KKT, 0,
             8, (long long)QQ * DD, 64, nullptr, 0, nullptr, 1.f, 0);
        norm_attn_kernel<<<(MQ * DD + 255) / 256, 256>>>();

        gemm(p_attn, ow_l, p_h, MQ, DD, DD, DD, 1,
             1, 0, 0, 1, 0, 0, 1, 0, 0, p_h, DD, nullptr, 1.f, 0);

        ln_kernel<<<MQ, 256>>>(p_h, p_norm, ln2g + l * DD, ln2b + l * DD);
        gemm(p_norm, f1w_l, p_ff, MQ, DFF, DD, DFF, 1,
             1, 0, 0, 1, 0, 0, 1, 0, 0, nullptr, 0, f1b_l, 1.f, 1);
        gemm(p_ff, f2w_l, p_h, MQ, DD, DFF, DD, 1,
             1, 0, 0, 1, 0, 0, 1, 0, 0, p_h, DD, f2b_l, 1.f, 0);
    }

    gemm(p_h, headw, out, MQ, NV, DD, NV, 1,
         1, 0, 0, 1, 0, 0, 1, 0, 0, nullptr, 0, headb, 1.f, 0);
}

// round 3
// speedup vs baseline: 2.6459x; 1.9391x over previous
#include <cuda_runtime.h>
#include <math.h>
#include <stdint.h>

#define BB   4
#define QQ   512
#define KKT  1024
#define DD   512
#define HH   8
#define DH   64
#define DFF  2048
#define NL   12
#define NV   332
#define MEML 512

// ---------------- scratch (static device globals; no allocation) ----------------
__device__ float g_h[BB*QQ*DD];
__device__ float g_norm[BB*QQ*DD];
__device__ float g_wh[BB*QQ*3*DD];
__device__ float g_whmem[3*DD];
__device__ float g_posemb[KKT*DD];
__device__ float g_rk[KKT*DD];
__device__ float g_qw[BB*HH*QQ*DH];
__device__ float g_qr[BB*HH*QQ*DH];
__device__ float g_kt[BB*HH*KKT*DH];
__device__ float g_vtd[BB*HH*DH*KKT];
__device__ float g_rkt[HH*KKT*DH];
__device__ float g_ac[(long)BB*HH*QQ*KKT];
__device__ float g_bd[(long)BB*HH*QQ*KKT];
__device__ float g_attn[BB*QQ*DD];
__device__ float g_ff[BB*QQ*DFF];
__device__ float g_gath[BB*QQ*DD];
__device__ float g_sums[BB*HH*QQ];

__device__ __forceinline__ float to_tf32(float x) {
    uint32_t u;
    asm("cvt.rna.tf32.f32 %0, %1;" : "=r"(u) : "f"(x));
    return __uint_as_float(u);
}

// ---------------- 128x128 tf32 tensor-core GEMM: C = alpha*A@B^T (+bias)(relu)(+add) ----
// A: [M,Kd] row-major, B: [N,Kd] row-major. Kd must be a multiple of 16,
// rows 16B-aligned (true at every call site). N edges guarded.
#define BM 128
#define BN 128
#define LDS_K 20   // 16 + 4 pad (floats); conflict-free fragment loads

__global__ __launch_bounds__(256, 2)
void gemm128(const float* __restrict__ A, const float* __restrict__ B,
             float* __restrict__ C,
             int M, int N, int Kd, int ldc,
             int zdA, long long hA, long long lA,
             int zdB, long long hB, long long lB,
             int zdC, long long hC, long long lC,
             const float* __restrict__ addsrc, int ldadd,
             const float* __restrict__ bias,
             float alpha, int relu)
{
    __shared__ float As[2][BM][LDS_K];
    __shared__ float Bs[2][BN][LDS_K];

    int z = blockIdx.z;
    A += (long long)(z / zdA) * hA + (long long)(z % zdA) * lA;
    B += (long long)(z / zdB) * hB + (long long)(z % zdB) * lB;
    C += (long long)(z / zdC) * hC + (long long)(z % zdC) * lC;

    int bm = blockIdx.y * BM, bn = blockIdx.x * BN;
    int tid  = threadIdx.x;
    int lane = tid & 31, warp = tid >> 5;
    int g  = lane >> 2, t4 = lane & 3;
    int wm = (warp >> 1) * 32;      // 4 warps down M
    int wn = (warp & 1) * 64;       // 2 warps across N

    // global->smem staging: 512 float4 per operand tile, 2 per thread
    int lrow = tid >> 2;            // 0..63 (+64 second trip)
    int lkq  = (tid & 3) * 4;       // 0,4,8,12

    float acc[2][8][4];
#pragma unroll
    for (int mt = 0; mt < 2; mt++)
#pragma unroll
        for (int nt = 0; nt < 8; nt++)
#pragma unroll
            for (int q = 0; q < 4; q++) acc[mt][nt][q] = 0.f;

    float4 pa[2], pb[2];

    auto ldgA = [&](int k0, int it) -> float4 {
        int gm = bm + lrow + it * 64;
        if (gm < M) return *(const float4*)&A[(long long)gm * Kd + k0 + lkq];
        return make_float4(0.f, 0.f, 0.f, 0.f);
    };
    auto ldgB = [&](int k0, int it) -> float4 {
        int gn = bn + lrow + it * 64;
        if (gn < N) return *(const float4*)&B[(long long)gn * Kd + k0 + lkq];
        return make_float4(0.f, 0.f, 0.f, 0.f);
    };
    auto stash = [&](int buf) {
#pragma unroll
        for (int it = 0; it < 2; it++) {
            int r = lrow + it * 64;
            float4 ta = make_float4(to_tf32(pa[it].x), to_tf32(pa[it].y),
                                    to_tf32(pa[it].z), to_tf32(pa[it].w));
            float4 tb = make_float4(to_tf32(pb[it].x), to_tf32(pb[it].y),
                                    to_tf32(pb[it].z), to_tf32(pb[it].w));
            *(float4*)&As[buf][r][lkq] = ta;
            *(float4*)&Bs[buf][r][lkq] = tb;
        }
    };

    int nk = Kd >> 4;
    pa[0] = ldgA(0, 0); pa[1] = ldgA(0, 1);
    pb[0] = ldgB(0, 0); pb[1] = ldgB(0, 1);
    stash(0);
    __syncthreads();

    int buf = 0;
    for (int t = 0; t < nk; t++) {
        int has_next = (t + 1 < nk);
        if (has_next) {
            int k0 = (t + 1) << 4;
            pa[0] = ldgA(k0, 0); pa[1] = ldgA(k0, 1);
            pb[0] = ldgB(k0, 0); pb[1] = ldgB(k0, 1);
        }
#pragma unroll
        for (int ks = 0; ks < 16; ks += 8) {
            uint32_t af[2][4];
#pragma unroll
            for (int mt = 0; mt < 2; mt++) {
                int m0 = wm + mt * 16 + g;
                af[mt][0] = __float_as_uint(As[buf][m0    ][ks + t4    ]);
                af[mt][1] = __float_as_uint(As[buf][m0 + 8][ks + t4    ]);
                af[mt][2] = __float_as_uint(As[buf][m0    ][ks + t4 + 4]);
                af[mt][3] = __float_as_uint(As[buf][m0 + 8][ks + t4 + 4]);
            }
#pragma unroll
            for (int nt = 0; nt < 8; nt++) {
                int n0 = wn + nt * 8 + g;
                uint32_t b0 = __float_as_uint(Bs[buf][n0][ks + t4    ]);
                uint32_t b1 = __float_as_uint(Bs[buf][n0][ks + t4 + 4]);
#pragma unroll
                for (int mt = 0; mt < 2; mt++) {
                    asm volatile(
                        "mma.sync.aligned.m16n8k8.row.col.f32.tf32.tf32.f32 "
                        "{%0,%1,%2,%3}, {%4,%5,%6,%7}, {%8,%9}, {%0,%1,%2,%3};"
                        : "+f"(acc[mt][nt][0]), "+f"(acc[mt][nt][1]),
                          "+f"(acc[mt][nt][2]), "+f"(acc[mt][nt][3])
                        : "r"(af[mt][0]), "r"(af[mt][1]),
                          "r"(af[mt][2]), "r"(af[mt][3]),
                          "r"(b0), "r"(b1));
                }
            }
        }
        if (has_next) {
            stash(buf ^ 1);
            __syncthreads();
            buf ^= 1;
        }
    }

    auto emit = [&](int gm, int gn, float v) {
        if (gm < M && gn < N) {
            v *= alpha;
            if (bias) v += bias[gn];
            if (relu) v = fmaxf(v, 0.f);
            if (addsrc) v += addsrc[(long long)gm * ldadd + gn];
            C[(long long)gm * ldc + gn] = v;
        }
    };
#pragma unroll
    for (int mt = 0; mt < 2; mt++) {
        int r0 = bm + wm + mt * 16 + g;
#pragma unroll
        for (int nt = 0; nt < 8; nt++) {
            int c0 = bn + wn + nt * 8 + t4 * 2;
            emit(r0,     c0,     acc[mt][nt][0]);
            emit(r0,     c0 + 1, acc[mt][nt][1]);
            emit(r0 + 8, c0,     acc[mt][nt][2]);
            emit(r0 + 8, c0 + 1, acc[mt][nt][3]);
        }
    }
}

// ---------------- layernorm over 512-wide rows ----------------
__global__ void ln_kernel(const float* __restrict__ x, float* __restrict__ y,
                          const float* __restrict__ g, const float* __restrict__ b)
{
    int row = blockIdx.x;
    const float* xr = x + (long long)row * DD;
    float* yr = y + (long long)row * DD;
    int tid = threadIdx.x;  // 256
    float v0 = xr[tid], v1 = xr[tid + 256];
    float s = v0 + v1, s2 = v0 * v0 + v1 * v1;
    __shared__ float sh[16];
#pragma unroll
    for (int o = 16; o > 0; o >>= 1) {
        s  += __shfl_xor_sync(0xffffffffu, s,  o);
        s2 += __shfl_xor_sync(0xffffffffu, s2, o);
    }
    if ((tid & 31) == 0) { sh[tid >> 5] = s; sh[(tid >> 5) + 8] = s2; }
    __syncthreads();
    __shared__ float mu_s, rs_s;
    if (tid == 0) {
        float S = 0.f, S2 = 0.f;
        for (int w = 0; w < 8; w++) { S += sh[w]; S2 += sh[w + 8]; }
        float mu = S / DD;
        float var = S2 / DD - mu * mu;
        mu_s = mu;
        rs_s = rsqrtf(var + 1e-3f);
    }
    __syncthreads();
    float mu = mu_s, rs = rs_s;
    yr[tid]       = (v0 - mu) * rs * g[tid]       + b[tid];
    yr[tid + 256] = (v1 - mu) * rs * g[tid + 256] + b[tid + 256];
}

__global__ void whmem_kernel(const float* __restrict__ qkvw, const float* __restrict__ lnb)
{
    int n = blockIdx.x * blockDim.x + threadIdx.x;
    if (n >= 3 * DD) return;
    const float* wr = qkvw + (long long)n * DD;
    float s = 0.f;
    for (int c = 0; c < DD; c++) s += lnb[c] * wr[c];
    g_whmem[n] = s;
}

__global__ void posemb_kernel()
{
    int idx = blockIdx.x * blockDim.x + threadIdx.x;
    if (idx >= KKT * DD) return;
    int p = idx / DD, c = idx % DD;
    float pos = (float)(KKT - 1 - p);
    int k = (c < 256) ? c : (c - 256);
    float invf = powf(10000.0f, -((float)(2 * k)) / 512.0f);
    float a = pos * invf;
    g_posemb[idx] = (c < 256) ? sinf(a) : cosf(a);
}

__global__ void gather_kernel(const int* __restrict__ ids, const float* __restrict__ emb)
{
    int idx = blockIdx.x * blockDim.x + threadIdx.x;
    if (idx >= BB * QQ * DD) return;
    int m = idx / DD, c = idx % DD;
    g_gath[idx] = emb[(long long)ids[m] * DD + c];
}

__global__ void packq_kernel(const float* __restrict__ rwb, const float* __restrict__ rrb)
{
    int idx = blockIdx.x * blockDim.x + threadIdx.x;
    if (idx >= BB * QQ * DD) return;
    int bq = idx / DD, c = idx % DD;
    int h = c >> 6, d = c & 63;
    int b = bq / QQ, i = bq % QQ;
    float qv = g_wh[(long long)bq * (3 * DD) + c];
    long long o = (((long long)(b * HH + h)) * QQ + i) * DH + d;
    g_qw[o] = qv + rwb[c];
    g_qr[o] = qv + rrb[c];
}

__global__ void packkv_kernel()
{
    int idx = blockIdx.x * blockDim.x + threadIdx.x;
    if (idx >= BB * HH * KKT * DH) return;
    int d = idx & 63;
    int j = (idx >> 6) & 1023;
    int bh = idx >> 16;
    int b = bh >> 3, h = bh & 7;
    int c = h * 64 + d;
    float kv, vv;
    if (j < MEML) {
        kv = g_whmem[DD + c];
        vv = g_whmem[2 * DD + c];
    } else {
        long long r = (long long)(b * QQ + (j - MEML)) * (3 * DD);
        kv = g_wh[r + DD + c];
        vv = g_wh[r + 2 * DD + c];
    }
    g_kt[idx] = kv;
    g_vtd[((long long)bh * DH + d) * KKT + j] = vv;
}

__global__ void packrk_kernel()
{
    int idx = blockIdx.x * blockDim.x + threadIdx.x;
    if (idx >= HH * KKT * DH) return;
    int d = idx & 63;
    int p = (idx >> 6) & 1023;
    int h = idx >> 16;
    g_rkt[idx] = g_rk[(long long)p * DD + h * 64 + d];
}

__global__ void softmax_kernel()
{
    long long blk = blockIdx.x;              // blk = bh*QQ + i
    int i = (int)(blk % QQ);
    float* ac = g_ac + blk * KKT;
    const float* bd = g_bd + blk * KKT;
    int jmax = i + MEML;
    int tid = threadIdx.x;                   // 256
    float mx = -3.0e38f;
    for (int j = tid; j <= jmax; j += 256) {
        float s = 0.125f * (ac[j] + bd[j - i + (QQ - 1)]);
        ac[j] = s;
        mx = fmaxf(mx, s);
    }
    __shared__ float sh[8];
#pragma unroll
    for (int o = 16; o > 0; o >>= 1) mx = fmaxf(mx, __shfl_xor_sync(0xffffffffu, mx, o));
    if ((tid & 31) == 0) sh[tid >> 5] = mx;
    __syncthreads();
    if (tid == 0) {
        float m = sh[0];
        for (int w = 1; w < 8; w++) m = fmaxf(m, sh[w]);
        sh[0] = m;
    }
    __syncthreads();
    mx = sh[0];
    __syncthreads();
    float sum = 0.f;
    for (int j = tid; j < KKT; j += 256) {
        float e = (j <= jmax) ? expf(ac[j] - mx) : 0.f;
        ac[j] = e;
        sum += e;
    }
#pragma unroll
    for (int o = 16; o > 0; o >>= 1) sum += __shfl_xor_sync(0xffffffffu, sum, o);
    if ((tid & 31) == 0) sh[tid >> 5] = sum;
    __syncthreads();
    if (tid == 0) {
        float s = 0.f;
        for (int w = 0; w < 8; w++) s += sh[w];
        g_sums[blk] = s;
    }
}

__global__ void norm_attn_kernel()
{
    int idx = blockIdx.x * blockDim.x + threadIdx.x;
    if (idx >= BB * QQ * DD) return;
    int bq = idx / DD, c = idx % DD;
    int b = bq / QQ, i = bq % QQ, h = c >> 6;
    g_attn[idx] /= g_sums[(long long)(b * HH + h) * QQ + i];
}

// ---------------- host ----------------
static void gemm(const float* A, const float* B, float* C,
                 int M, int N, int K, int ldc, int nz,
                 int zdA, long long hA, long long lA,
                 int zdB, long long hB, long long lB,
                 int zdC, long long hC, long long lC,
                 const float* add, int ldadd, const float* bias,
                 float alpha, int relu)
{
    dim3 grid((N + BN - 1) / BN, (M + BM - 1) / BM, nz);
    gemm128<<<grid, 256>>>(A, B, C, M, N, K, ldc,
                           zdA, hA, lA, zdB, hB, lB, zdC, hC, lC,
                           add, ldadd, bias, alpha, relu);
}

extern "C" void kernel_launch(void* const* d_in, const int* in_sizes, int n_in,
                              void* d_out, int out_size)
{
    const int*   ids      = (const int*)d_in[0];
    const float* emb      = (const float*)d_in[1];
    const float* emb_proj = (const float*)d_in[2];
    const float* rwb      = (const float*)d_in[3];
    const float* rrb      = (const float*)d_in[4];
    const float* qkv_w    = (const float*)d_in[5];
    const float* o_w      = (const float*)d_in[6];
    const float* rnet_w   = (const float*)d_in[7];
    const float* ln1g     = (const float*)d_in[8];
    const float* ln1b     = (const float*)d_in[9];
    const float* ff1w     = (const float*)d_in[10];
    const float* ff1b     = (const float*)d_in[11];
    const float* ff2w     = (const float*)d_in[12];
    const float* ff2b     = (const float*)d_in[13];
    const float* ln2g     = (const float*)d_in[14];
    const float* ln2b     = (const float*)d_in[15];
    const float* headw    = (const float*)d_in[16];
    const float* headb    = (const float*)d_in[17];
    float* out = (float*)d_out;

    float *p_h, *p_norm, *p_wh, *p_posemb, *p_rk, *p_qw, *p_qr, *p_kt, *p_vtd,
          *p_rkt, *p_ac, *p_bd, *p_attn, *p_ff, *p_gath;
    void* tmp;
#define SYM(v, s) cudaGetSymbolAddress(&tmp, s); v = (float*)tmp;
    SYM(p_h, g_h) SYM(p_norm, g_norm) SYM(p_wh, g_wh) SYM(p_posemb, g_posemb)
    SYM(p_rk, g_rk) SYM(p_qw, g_qw) SYM(p_qr, g_qr) SYM(p_kt, g_kt)
    SYM(p_vtd, g_vtd) SYM(p_rkt, g_rkt) SYM(p_ac, g_ac) SYM(p_bd, g_bd)
    SYM(p_attn, g_attn) SYM(p_ff, g_ff) SYM(p_gath, g_gath)
#undef SYM

    const int MQ = BB * QQ;  // 2048 token rows

    gather_kernel<<<(MQ * DD + 255) / 256, 256>>>(ids, emb);
    posemb_kernel<<<(KKT * DD + 255) / 256, 256>>>();
    gemm(p_gath, emb_proj, p_h, MQ, DD, DD, DD, 1,
         1, 0, 0, 1, 0, 0, 1, 0, 0, nullptr, 0, nullptr, sqrtf((float)DD), 0);

    for (int l = 0; l < NL; l++) {
        const float* qkvw_l = qkv_w + (long long)l * 3 * DD * DD;
        const float* ow_l   = o_w   + (long long)l * DD * DD;
        const float* rnw_l  = rnet_w+ (long long)l * DD * DD;
        const float* f1w_l  = ff1w  + (long long)l * DFF * DD;
        const float* f1b_l  = ff1b  + (long long)l * DFF;
        const float* f2w_l  = ff2w  + (long long)l * DD * DFF;
        const float* f2b_l  = ff2b  + (long long)l * DD;

        ln_kernel<<<MQ, 256>>>(p_h, p_norm, ln1g + l * DD, ln1b + l * DD);
        whmem_kernel<<<12, 128>>>(qkvw_l, ln1b + l * DD);
        gemm(p_norm, qkvw_l, p_wh, MQ, 3 * DD, DD, 3 * DD, 1,
             1, 0, 0, 1, 0, 0, 1, 0, 0, nullptr, 0, nullptr, 1.f, 0);

        gemm(p_posemb, rnw_l, p_rk, KKT, DD, DD, DD, 1,
             1, 0, 0, 1, 0, 0, 1, 0, 0, nullptr, 0, nullptr, 1.f, 0);

        packq_kernel<<<(MQ * DD + 255) / 256, 256>>>(rwb, rrb);
        packkv_kernel<<<(BB * HH * KKT * DH + 255) / 256, 256>>>();
        packrk_kernel<<<(HH * KKT * DH + 255) / 256, 256>>>();

        gemm(p_qw, p_kt, p_ac, QQ, KKT, DH, KKT, BB * HH,
             1, (long long)QQ * DH, 0,
             1, (long long)KKT * DH, 0,
             1, (long long)QQ * KKT, 0, nullptr, 0, nullptr, 1.f, 0);
        gemm(p_qr, p_rkt, p_bd, QQ, KKT, DH, KKT, BB * HH,
             1, (long long)QQ * DH, 0,
             8, 0, (long long)KKT * DH,
             1, (long long)QQ * KKT, 0, nullptr, 0, nullptr, 1.f, 0);

        softmax_kernel<<<BB * HH * QQ, 256>>>();

        gemm(p_ac, p_vtd, p_attn, QQ, DH, KKT, DD, BB * HH,
             1, (long long)QQ * KKT, 0,
             1, (long long)DH * KKT, 0,
             8, (long long)QQ * DD, 64, nullptr, 0, nullptr, 1.f, 0);
        norm_attn_kernel<<<(MQ * DD + 255) / 256, 256>>>();

        gemm(p_attn, ow_l, p_h, MQ, DD, DD, DD, 1,
             1, 0, 0, 1, 0, 0, 1, 0, 0, p_h, DD, nullptr, 1.f, 0);

        ln_kernel<<<MQ, 256>>>(p_h, p_norm, ln2g + l * DD, ln2b + l * DD);
        gemm(p_norm, f1w_l, p_ff, MQ, DFF, DD, DFF, 1,
             1, 0, 0, 1, 0, 0, 1, 0, 0, nullptr, 0, f1b_l, 1.f, 1);
        gemm(p_ff, f2w_l, p_h, MQ, DD, DFF, DD, 1,
             1, 0, 0, 1, 0, 0, 1, 0, 0, p_h, DD, f2b_l, 1.f, 0);
    }

    gemm(p_h, headw, out, MQ, NV, DD, NV, 1,
         1, 0, 0, 1, 0, 0, 1, 0, 0, nullptr, 0, headb, 1.f, 0);
}

// round 4
// speedup vs baseline: 2.6895x; 1.0165x over previous
#include <cuda_runtime.h>
#include <math.h>
#include <stdint.h>

#define BB   4
#define QQ   512
#define KKT  1024
#define DD   512
#define HH   8
#define DH   64
#define DFF  2048
#define NL   12
#define NV   332
#define MEML 512
#define UW   128                 // rk shift window width
#define RKP  (KKT + UW)          // padded rk rows (zeros beyond 1023)

// ---------------- scratch (static device globals; no allocation) ----------------
__device__ float g_h[BB*QQ*DD];
__device__ float g_norm[BB*QQ*DD];
__device__ float g_wh[BB*QQ*3*DD];
__device__ float g_whmem[3*DD];
__device__ float g_posemb[KKT*DD];
__device__ float g_rk[KKT*DD];
__device__ float g_q[BB*HH*QQ*DH];       // Q, head-major (no bias added)
__device__ float g_kt[BB*HH*KKT*DH];     // K, [bh][j][d]
__device__ float g_vtd[BB*HH*DH*KKT];    // V, [bh][d][j]
__device__ float g_rkt[HH*RKP*DH];       // rk, [h][u][d], zero-padded
__device__ float g_bw[BB*HH*KKT];        // rwb_h . k_j
__device__ float g_br[HH*RKP];           // rrb_h . rk_u (zero-padded)
__device__ float g_attn[BB*QQ*DD];
__device__ float g_ff[BB*QQ*DFF];
__device__ float g_gath[BB*QQ*DD];

__device__ __forceinline__ float to_tf32(float x) {
    uint32_t u;
    asm("cvt.rna.tf32.f32 %0, %1;" : "=r"(u) : "f"(x));
    return __uint_as_float(u);
}

#define MMA_TF32(acc, a0,a1,a2,a3, b0,b1) \
    asm volatile("mma.sync.aligned.m16n8k8.row.col.f32.tf32.tf32.f32 " \
                 "{%0,%1,%2,%3}, {%4,%5,%6,%7}, {%8,%9}, {%0,%1,%2,%3};" \
                 : "+f"(acc[0]), "+f"(acc[1]), "+f"(acc[2]), "+f"(acc[3]) \
                 : "r"(a0), "r"(a1), "r"(a2), "r"(a3), "r"(b0), "r"(b1))

// ---------------- 128x128 tf32 tensor-core GEMM (unchanged from R3) ----------------
#define BM 128
#define BN 128
#define LDS_K 20

__global__ __launch_bounds__(256, 2)
void gemm128(const float* __restrict__ A, const float* __restrict__ B,
             float* __restrict__ C,
             int M, int N, int Kd, int ldc,
             int zdA, long long hA, long long lA,
             int zdB, long long hB, long long lB,
             int zdC, long long hC, long long lC,
             const float* __restrict__ addsrc, int ldadd,
             const float* __restrict__ bias,
             float alpha, int relu)
{
    __shared__ float As[2][BM][LDS_K];
    __shared__ float Bs[2][BN][LDS_K];

    int z = blockIdx.z;
    A += (long long)(z / zdA) * hA + (long long)(z % zdA) * lA;
    B += (long long)(z / zdB) * hB + (long long)(z % zdB) * lB;
    C += (long long)(z / zdC) * hC + (long long)(z % zdC) * lC;

    int bm = blockIdx.y * BM, bn = blockIdx.x * BN;
    int tid  = threadIdx.x;
    int lane = tid & 31, warp = tid >> 5;
    int g  = lane >> 2, t4 = lane & 3;
    int wm = (warp >> 1) * 32;
    int wn = (warp & 1) * 64;

    int lrow = tid >> 2;
    int lkq  = (tid & 3) * 4;

    float acc[2][8][4];
#pragma unroll
    for (int mt = 0; mt < 2; mt++)
#pragma unroll
        for (int nt = 0; nt < 8; nt++)
#pragma unroll
            for (int q = 0; q < 4; q++) acc[mt][nt][q] = 0.f;

    float4 pa[2], pb[2];

    auto ldgA = [&](int k0, int it) -> float4 {
        int gm = bm + lrow + it * 64;
        if (gm < M) return *(const float4*)&A[(long long)gm * Kd + k0 + lkq];
        return make_float4(0.f, 0.f, 0.f, 0.f);
    };
    auto ldgB = [&](int k0, int it) -> float4 {
        int gn = bn + lrow + it * 64;
        if (gn < N) return *(const float4*)&B[(long long)gn * Kd + k0 + lkq];
        return make_float4(0.f, 0.f, 0.f, 0.f);
    };
    auto stash = [&](int buf) {
#pragma unroll
        for (int it = 0; it < 2; it++) {
            int r = lrow + it * 64;
            float4 ta = make_float4(to_tf32(pa[it].x), to_tf32(pa[it].y),
                                    to_tf32(pa[it].z), to_tf32(pa[it].w));
            float4 tb = make_float4(to_tf32(pb[it].x), to_tf32(pb[it].y),
                                    to_tf32(pb[it].z), to_tf32(pb[it].w));
            *(float4*)&As[buf][r][lkq] = ta;
            *(float4*)&Bs[buf][r][lkq] = tb;
        }
    };

    int nk = Kd >> 4;
    pa[0] = ldgA(0, 0); pa[1] = ldgA(0, 1);
    pb[0] = ldgB(0, 0); pb[1] = ldgB(0, 1);
    stash(0);
    __syncthreads();

    int buf = 0;
    for (int t = 0; t < nk; t++) {
        int has_next = (t + 1 < nk);
        if (has_next) {
            int k0 = (t + 1) << 4;
            pa[0] = ldgA(k0, 0); pa[1] = ldgA(k0, 1);
            pb[0] = ldgB(k0, 0); pb[1] = ldgB(k0, 1);
        }
#pragma unroll
        for (int ks = 0; ks < 16; ks += 8) {
            uint32_t af[2][4];
#pragma unroll
            for (int mt = 0; mt < 2; mt++) {
                int m0 = wm + mt * 16 + g;
                af[mt][0] = __float_as_uint(As[buf][m0    ][ks + t4    ]);
                af[mt][1] = __float_as_uint(As[buf][m0 + 8][ks + t4    ]);
                af[mt][2] = __float_as_uint(As[buf][m0    ][ks + t4 + 4]);
                af[mt][3] = __float_as_uint(As[buf][m0 + 8][ks + t4 + 4]);
            }
#pragma unroll
            for (int nt = 0; nt < 8; nt++) {
                int n0 = wn + nt * 8 + g;
                uint32_t b0 = __float_as_uint(Bs[buf][n0][ks + t4    ]);
                uint32_t b1 = __float_as_uint(Bs[buf][n0][ks + t4 + 4]);
#pragma unroll
                for (int mt = 0; mt < 2; mt++)
                    MMA_TF32(acc[mt][nt], af[mt][0], af[mt][1], af[mt][2], af[mt][3], b0, b1);
            }
        }
        if (has_next) {
            stash(buf ^ 1);
            __syncthreads();
            buf ^= 1;
        }
    }

    auto emit = [&](int gm, int gn, float v) {
        if (gm < M && gn < N) {
            v *= alpha;
            if (bias) v += bias[gn];
            if (relu) v = fmaxf(v, 0.f);
            if (addsrc) v += addsrc[(long long)gm * ldadd + gn];
            C[(long long)gm * ldc + gn] = v;
        }
    };
#pragma unroll
    for (int mt = 0; mt < 2; mt++) {
        int r0 = bm + wm + mt * 16 + g;
#pragma unroll
        for (int nt = 0; nt < 8; nt++) {
            int c0 = bn + wn + nt * 8 + t4 * 2;
            emit(r0,     c0,     acc[mt][nt][0]);
            emit(r0,     c0 + 1, acc[mt][nt][1]);
            emit(r0 + 8, c0,     acc[mt][nt][2]);
            emit(r0 + 8, c0 + 1, acc[mt][nt][3]);
        }
    }
}

// ---------------- fused flash attention with rel_shift ----------------
#define SQS 68     // smem stride for 64-col tiles
#define STS 132    // smem stride for T (128-col)

__global__ __launch_bounds__(128, 1)
void attn_kernel()
{
    extern __shared__ float sm[];
    float* sQ  = sm;                       // 64 x SQS
    float* sK  = sQ  + 64 * SQS;           // 64 x SQS
    float* sV  = sK  + 64 * SQS;           // Vt: [d][j], 64 x SQS
    float* sRK = sV  + 64 * SQS;           // 128 x SQS ; reused as P (64 x SQS)
    float* sT  = sRK + UW * SQS;           // 64 x STS
    float* sBW = sT  + 64 * STS;           // 64
    float* sBR = sBW + 64;                 // 128

    int it = blockIdx.x;                   // i-tile (0..7)
    int bh = blockIdx.y;                   // 0..31
    int h  = bh & 7, b = bh >> 3;
    int i0 = it * 64;
    int tid  = threadIdx.x;
    int lane = tid & 31, warp = tid >> 5;
    int g = lane >> 2, t4 = lane & 3;
    int wr = warp * 16;

    const float* Qg  = g_q   + ((long long)bh * QQ) * DH + (long long)i0 * DH;
    const float* Kg  = g_kt  + (long long)bh * KKT * DH;
    const float* Vg  = g_vtd + (long long)bh * DH * KKT;
    const float* RKg = g_rkt + (long long)h * RKP * DH;

    // load Q tile once (tf32)
    {
        int r = tid >> 1, half = (tid & 1) * 32;
        const float* src = Qg + r * DH + half;
        float* dst = sQ + r * SQS + half;
#pragma unroll
        for (int q = 0; q < 8; q++) {
            float4 v = *(const float4*)(src + q * 4);
            dst[q*4+0] = to_tf32(v.x); dst[q*4+1] = to_tf32(v.y);
            dst[q*4+2] = to_tf32(v.z); dst[q*4+3] = to_tf32(v.w);
        }
    }

    float mrow[2] = {-1e30f, -1e30f};
    float lrow[2] = {0.f, 0.f};
    float O[8][4];
#pragma unroll
    for (int nt = 0; nt < 8; nt++)
#pragma unroll
        for (int q = 0; q < 4; q++) O[nt][q] = 0.f;

    int njt = it + 9;
    for (int jt = 0; jt < njt; jt++) {
        int j0 = jt * 64;
        int ub = j0 - i0 + 448;            // >= 0 always
        __syncthreads();                   // P reads (prev iter) done before overwrite
        // load K and Vt tiles
        {
            int r = tid >> 1, half = (tid & 1) * 32;
            const float* ks = Kg + (long long)(j0 + r) * DH + half;
            float* kd = sK + r * SQS + half;
            const float* vs = Vg + (long long)r * KKT + j0 + half;
            float* vd = sV + r * SQS + half;
#pragma unroll
            for (int q = 0; q < 8; q++) {
                float4 v = *(const float4*)(ks + q * 4);
                kd[q*4+0] = to_tf32(v.x); kd[q*4+1] = to_tf32(v.y);
                kd[q*4+2] = to_tf32(v.z); kd[q*4+3] = to_tf32(v.w);
                float4 w = *(const float4*)(vs + q * 4);
                vd[q*4+0] = to_tf32(w.x); vd[q*4+1] = to_tf32(w.y);
                vd[q*4+2] = to_tf32(w.z); vd[q*4+3] = to_tf32(w.w);
            }
        }
        // load RK window (128 rows, one per thread)
        {
            const float* rs = RKg + (long long)(ub + tid) * DH;
            float* rd = sRK + tid * SQS;
#pragma unroll
            for (int q = 0; q < 16; q++) {
                float4 v = *(const float4*)(rs + q * 4);
                rd[q*4+0] = to_tf32(v.x); rd[q*4+1] = to_tf32(v.y);
                rd[q*4+2] = to_tf32(v.z); rd[q*4+3] = to_tf32(v.w);
            }
        }
        if (tid < 64) sBW[tid] = g_bw[(long long)bh * KKT + j0 + tid];
        sBR[tid] = g_br[h * RKP + ub + tid];
        __syncthreads();

        // MMA: AC (regs) + T (SMEM)
        float ac[8][4];
        float tf[16][4];
#pragma unroll
        for (int nt = 0; nt < 8; nt++)
#pragma unroll
            for (int q = 0; q < 4; q++) ac[nt][q] = 0.f;
#pragma unroll
        for (int nt = 0; nt < 16; nt++)
#pragma unroll
            for (int q = 0; q < 4; q++) tf[nt][q] = 0.f;

#pragma unroll
        for (int ks = 0; ks < 64; ks += 8) {
            uint32_t a0 = __float_as_uint(sQ[(wr + g    ) * SQS + ks + t4    ]);
            uint32_t a1 = __float_as_uint(sQ[(wr + g + 8) * SQS + ks + t4    ]);
            uint32_t a2 = __float_as_uint(sQ[(wr + g    ) * SQS + ks + t4 + 4]);
            uint32_t a3 = __float_as_uint(sQ[(wr + g + 8) * SQS + ks + t4 + 4]);
#pragma unroll
            for (int nt = 0; nt < 8; nt++) {
                uint32_t b0 = __float_as_uint(sK[(nt * 8 + g) * SQS + ks + t4    ]);
                uint32_t b1 = __float_as_uint(sK[(nt * 8 + g) * SQS + ks + t4 + 4]);
                MMA_TF32(ac[nt], a0, a1, a2, a3, b0, b1);
            }
#pragma unroll
            for (int nt = 0; nt < 16; nt++) {
                uint32_t b0 = __float_as_uint(sRK[(nt * 8 + g) * SQS + ks + t4    ]);
                uint32_t b1 = __float_as_uint(sRK[(nt * 8 + g) * SQS + ks + t4 + 4]);
                MMA_TF32(tf[nt], a0, a1, a2, a3, b0, b1);
            }
        }
        // T accumulators -> SMEM
#pragma unroll
        for (int nt = 0; nt < 16; nt++) {
            int c = nt * 8 + t4 * 2;
            sT[(wr + g    ) * STS + c    ] = tf[nt][0];
            sT[(wr + g    ) * STS + c + 1] = tf[nt][1];
            sT[(wr + g + 8) * STS + c    ] = tf[nt][2];
            sT[(wr + g + 8) * STS + c + 1] = tf[nt][3];
        }
        __syncthreads();

        // scores + online softmax (in-place in ac)
        int last = (j0 - i0 == 512);
        float mt2[2] = {-1e30f, -1e30f};
#pragma unroll
        for (int nt = 0; nt < 8; nt++) {
            int jl0 = nt * 8 + t4 * 2;
#pragma unroll
            for (int r2 = 0; r2 < 2; r2++) {
                int il = wr + g + r2 * 8;
#pragma unroll
                for (int cc = 0; cc < 2; cc++) {
                    int jl = jl0 + cc;
                    int ul = jl - il + 63;
                    float s = (ac[nt][r2*2+cc] + sBW[jl] + sT[il * STS + ul] + sBR[ul]) * 0.125f;
                    if (last && jl > il) s = -1e30f;
                    ac[nt][r2*2+cc] = s;
                    mt2[r2] = fmaxf(mt2[r2], s);
                }
            }
        }
#pragma unroll
        for (int r2 = 0; r2 < 2; r2++) {
            mt2[r2] = fmaxf(mt2[r2], __shfl_xor_sync(0xffffffffu, mt2[r2], 1));
            mt2[r2] = fmaxf(mt2[r2], __shfl_xor_sync(0xffffffffu, mt2[r2], 2));
        }
        float corr[2], ls[2] = {0.f, 0.f};
#pragma unroll
        for (int r2 = 0; r2 < 2; r2++) {
            float mnew = fmaxf(mrow[r2], mt2[r2]);
            corr[r2] = __expf(mrow[r2] - mnew);
            mrow[r2] = mnew;
        }
#pragma unroll
        for (int nt = 0; nt < 8; nt++)
#pragma unroll
            for (int r2 = 0; r2 < 2; r2++)
#pragma unroll
                for (int cc = 0; cc < 2; cc++) {
                    float e = __expf(ac[nt][r2*2+cc] - mrow[r2]);
                    ac[nt][r2*2+cc] = e;
                    ls[r2] += e;
                }
#pragma unroll
        for (int r2 = 0; r2 < 2; r2++) {
            ls[r2] += __shfl_xor_sync(0xffffffffu, ls[r2], 1);
            ls[r2] += __shfl_xor_sync(0xffffffffu, ls[r2], 2);
            lrow[r2] = lrow[r2] * corr[r2] + ls[r2];
        }
#pragma unroll
        for (int nt = 0; nt < 8; nt++)
#pragma unroll
            for (int q = 0; q < 4; q++) O[nt][q] *= corr[q >> 1];

        // P (tf32) -> reuse sRK region
#pragma unroll
        for (int nt = 0; nt < 8; nt++) {
            int c = nt * 8 + t4 * 2;
            sRK[(wr + g    ) * SQS + c    ] = to_tf32(ac[nt][0]);
            sRK[(wr + g    ) * SQS + c + 1] = to_tf32(ac[nt][1]);
            sRK[(wr + g + 8) * SQS + c    ] = to_tf32(ac[nt][2]);
            sRK[(wr + g + 8) * SQS + c + 1] = to_tf32(ac[nt][3]);
        }
        __syncthreads();

        // O += P @ Vt^T
#pragma unroll
        for (int ks = 0; ks < 64; ks += 8) {
            uint32_t a0 = __float_as_uint(sRK[(wr + g    ) * SQS + ks + t4    ]);
            uint32_t a1 = __float_as_uint(sRK[(wr + g + 8) * SQS + ks + t4    ]);
            uint32_t a2 = __float_as_uint(sRK[(wr + g    ) * SQS + ks + t4 + 4]);
            uint32_t a3 = __float_as_uint(sRK[(wr + g + 8) * SQS + ks + t4 + 4]);
#pragma unroll
            for (int nt = 0; nt < 8; nt++) {
                uint32_t b0 = __float_as_uint(sV[(nt * 8 + g) * SQS + ks + t4    ]);
                uint32_t b1 = __float_as_uint(sV[(nt * 8 + g) * SQS + ks + t4 + 4]);
                MMA_TF32(O[nt], a0, a1, a2, a3, b0, b1);
            }
        }
    }

    // epilogue: normalize and scatter to g_attn [b][i][h*64+d]
    float inv0 = 1.f / lrow[0], inv1 = 1.f / lrow[1];
    long long r0 = (long long)(b * QQ + i0 + wr + g) * DD + h * 64;
    long long r1 = (long long)(b * QQ + i0 + wr + g + 8) * DD + h * 64;
#pragma unroll
    for (int nt = 0; nt < 8; nt++) {
        int c = nt * 8 + t4 * 2;
        g_attn[r0 + c]     = O[nt][0] * inv0;
        g_attn[r0 + c + 1] = O[nt][1] * inv0;
        g_attn[r1 + c]     = O[nt][2] * inv1;
        g_attn[r1 + c + 1] = O[nt][3] * inv1;
    }
}

// ---------------- layernorm over 512-wide rows ----------------
__global__ void ln_kernel(const float* __restrict__ x, float* __restrict__ y,
                          const float* __restrict__ g, const float* __restrict__ b)
{
    int row = blockIdx.x;
    const float* xr = x + (long long)row * DD;
    float* yr = y + (long long)row * DD;
    int tid = threadIdx.x;  // 256
    float v0 = xr[tid], v1 = xr[tid + 256];
    float s = v0 + v1, s2 = v0 * v0 + v1 * v1;
    __shared__ float sh[16];
#pragma unroll
    for (int o = 16; o > 0; o >>= 1) {
        s  += __shfl_xor_sync(0xffffffffu, s,  o);
        s2 += __shfl_xor_sync(0xffffffffu, s2, o);
    }
    if ((tid & 31) == 0) { sh[tid >> 5] = s; sh[(tid >> 5) + 8] = s2; }
    __syncthreads();
    __shared__ float mu_s, rs_s;
    if (tid == 0) {
        float S = 0.f, S2 = 0.f;
        for (int w = 0; w < 8; w++) { S += sh[w]; S2 += sh[w + 8]; }
        float mu = S / DD;
        float var = S2 / DD - mu * mu;
        mu_s = mu;
        rs_s = rsqrtf(var + 1e-3f);
    }
    __syncthreads();
    float mu = mu_s, rs = rs_s;
    yr[tid]       = (v0 - mu) * rs * g[tid]       + b[tid];
    yr[tid + 256] = (v1 - mu) * rs * g[tid + 256] + b[tid + 256];
}

__global__ void whmem_kernel(const float* __restrict__ qkvw, const float* __restrict__ lnb)
{
    int n = blockIdx.x * blockDim.x + threadIdx.x;
    if (n >= 3 * DD) return;
    const float* wr = qkvw + (long long)n * DD;
    float s = 0.f;
    for (int c = 0; c < DD; c++) s += lnb[c] * wr[c];
    g_whmem[n] = s;
}

__global__ void posemb_kernel()
{
    int idx = blockIdx.x * blockDim.x + threadIdx.x;
    if (idx >= KKT * DD) return;
    int p = idx / DD, c = idx % DD;
    float pos = (float)(KKT - 1 - p);
    int k = (c < 256) ? c : (c - 256);
    float invf = powf(10000.0f, -((float)(2 * k)) / 512.0f);
    float a = pos * invf;
    g_posemb[idx] = (c < 256) ? sinf(a) : cosf(a);
}

__global__ void gather_kernel(const int* __restrict__ ids, const float* __restrict__ emb)
{
    int idx = blockIdx.x * blockDim.x + threadIdx.x;
    if (idx >= BB * QQ * DD) return;
    int m = idx / DD, c = idx % DD;
    g_gath[idx] = emb[(long long)ids[m] * DD + c];
}

__global__ void packq_kernel()
{
    int idx = blockIdx.x * blockDim.x + threadIdx.x;
    if (idx >= BB * QQ * DD) return;
    int bq = idx / DD, c = idx % DD;
    int h = c >> 6, d = c & 63;
    int b = bq / QQ, i = bq % QQ;
    g_q[(((long long)(b * HH + h)) * QQ + i) * DH + d] = g_wh[(long long)bq * (3 * DD) + c];
}

__global__ void packkv_kernel()
{
    int idx = blockIdx.x * blockDim.x + threadIdx.x;
    if (idx >= BB * HH * KKT * DH) return;
    int d = idx & 63;
    int j = (idx >> 6) & 1023;
    int bh = idx >> 16;
    int b = bh >> 3, h = bh & 7;
    int c = h * 64 + d;
    float kv, vv;
    if (j < MEML) {
        kv = g_whmem[DD + c];
        vv = g_whmem[2 * DD + c];
    } else {
        long long r = (long long)(b * QQ + (j - MEML)) * (3 * DD);
        kv = g_wh[r + DD + c];
        vv = g_wh[r + 2 * DD + c];
    }
    g_kt[idx] = kv;
    g_vtd[((long long)bh * DH + d) * KKT + j] = vv;
}

__global__ void packrk_kernel()
{
    int idx = blockIdx.x * blockDim.x + threadIdx.x;
    if (idx >= HH * RKP * DH) return;
    int d = idx & 63;
    int p = (idx >> 6) % RKP;
    int h = idx / (RKP * DH);
    g_rkt[idx] = (p < KKT) ? g_rk[(long long)p * DD + h * 64 + d] : 0.f;
}

// bw[bh][j] = rwb_h . K[bh][j]
__global__ void bw_kernel(const float* __restrict__ rwb)
{
    int idx = blockIdx.x * blockDim.x + threadIdx.x;
    if (idx >= BB * HH * KKT) return;
    int bh = idx >> 10, j = idx & 1023;
    int h = bh & 7;
    const float* kr = g_kt + ((long long)bh * KKT + j) * DH;
    const float* w = rwb + h * DH;
    float s = 0.f;
#pragma unroll
    for (int d = 0; d < DH; d++) s += w[d] * kr[d];
    g_bw[idx] = s;
}

// br[h][u] = rrb_h . rk[h][u] (0 beyond 1023)
__global__ void br_kernel(const float* __restrict__ rrb)
{
    int idx = blockIdx.x * blockDim.x + threadIdx.x;
    if (idx >= HH * RKP) return;
    int h = idx / RKP, u = idx % RKP;
    float s = 0.f;
    if (u < KKT) {
        const float* rr = g_rk + (long long)u * DD + h * 64;
        const float* w = rrb + h * DH;
#pragma unroll
        for (int d = 0; d < DH; d++) s += w[d] * rr[d];
    }
    g_br[idx] = s;
}

// ---------------- host ----------------
static void gemm(const float* A, const float* B, float* C,
                 int M, int N, int K, int ldc, int nz,
                 int zdA, long long hA, long long lA,
                 int zdB, long long hB, long long lB,
                 int zdC, long long hC, long long lC,
                 const float* add, int ldadd, const float* bias,
                 float alpha, int relu)
{
    dim3 grid((N + BN - 1) / BN, (M + BM - 1) / BM, nz);
    gemm128<<<grid, 256>>>(A, B, C, M, N, K, ldc,
                           zdA, hA, lA, zdB, hB, lB, zdC, hC, lC,
                           add, ldadd, bias, alpha, relu);
}

extern "C" void kernel_launch(void* const* d_in, const int* in_sizes, int n_in,
                              void* d_out, int out_size)
{
    const int*   ids      = (const int*)d_in[0];
    const float* emb      = (const float*)d_in[1];
    const float* emb_proj = (const float*)d_in[2];
    const float* rwb      = (const float*)d_in[3];
    const float* rrb      = (const float*)d_in[4];
    const float* qkv_w    = (const float*)d_in[5];
    const float* o_w      = (const float*)d_in[6];
    const float* rnet_w   = (const float*)d_in[7];
    const float* ln1g     = (const float*)d_in[8];
    const float* ln1b     = (const float*)d_in[9];
    const float* ff1w     = (const float*)d_in[10];
    const float* ff1b     = (const float*)d_in[11];
    const float* ff2w     = (const float*)d_in[12];
    const float* ff2b     = (const float*)d_in[13];
    const float* ln2g     = (const float*)d_in[14];
    const float* ln2b     = (const float*)d_in[15];
    const float* headw    = (const float*)d_in[16];
    const float* headb    = (const float*)d_in[17];
    float* out = (float*)d_out;

    float *p_h, *p_norm, *p_wh, *p_posemb, *p_rk, *p_attn, *p_ff, *p_gath;
    void* tmp;
#define SYM(v, s) cudaGetSymbolAddress(&tmp, s); v = (float*)tmp;
    SYM(p_h, g_h) SYM(p_norm, g_norm) SYM(p_wh, g_wh) SYM(p_posemb, g_posemb)
    SYM(p_rk, g_rk) SYM(p_attn, g_attn) SYM(p_ff, g_ff) SYM(p_gath, g_gath)
#undef SYM

    const int ATTN_SMEM = (3 * 64 * SQS + UW * SQS + 64 * STS + 64 + 128) * 4;
    cudaFuncSetAttribute(attn_kernel, cudaFuncAttributeMaxDynamicSharedMemorySize, ATTN_SMEM);

    const int MQ = BB * QQ;  // 2048 token rows

    gather_kernel<<<(MQ * DD + 255) / 256, 256>>>(ids, emb);
    posemb_kernel<<<(KKT * DD + 255) / 256, 256>>>();
    gemm(p_gath, emb_proj, p_h, MQ, DD, DD, DD, 1,
         1, 0, 0, 1, 0, 0, 1, 0, 0, nullptr, 0, nullptr, sqrtf((float)DD), 0);

    for (int l = 0; l < NL; l++) {
        const float* qkvw_l = qkv_w + (long long)l * 3 * DD * DD;
        const float* ow_l   = o_w   + (long long)l * DD * DD;
        const float* rnw_l  = rnet_w+ (long long)l * DD * DD;
        const float* f1w_l  = ff1w  + (long long)l * DFF * DD;
        const float* f1b_l  = ff1b  + (long long)l * DFF;
        const float* f2w_l  = ff2w  + (long long)l * DD * DFF;
        const float* f2b_l  = ff2b  + (long long)l * DD;

        ln_kernel<<<MQ, 256>>>(p_h, p_norm, ln1g + l * DD, ln1b + l * DD);
        whmem_kernel<<<12, 128>>>(qkvw_l, ln1b + l * DD);
        gemm(p_norm, qkvw_l, p_wh, MQ, 3 * DD, DD, 3 * DD, 1,
             1, 0, 0, 1, 0, 0, 1, 0, 0, nullptr, 0, nullptr, 1.f, 0);

        gemm(p_posemb, rnw_l, p_rk, KKT, DD, DD, DD, 1,
             1, 0, 0, 1, 0, 0, 1, 0, 0, nullptr, 0, nullptr, 1.f, 0);

        packq_kernel<<<(MQ * DD + 255) / 256, 256>>>();
        packkv_kernel<<<(BB * HH * KKT * DH + 255) / 256, 256>>>();
        packrk_kernel<<<(HH * RKP * DH + 255) / 256, 256>>>();
        bw_kernel<<<(BB * HH * KKT + 255) / 256, 256>>>(rwb);
        br_kernel<<<(HH * RKP + 255) / 256, 256>>>(rrb);

        attn_kernel<<<dim3(QQ / 64, BB * HH), 128, ATTN_SMEM>>>();

        gemm(p_attn, ow_l, p_h, MQ, DD, DD, DD, 1,
             1, 0, 0, 1, 0, 0, 1, 0, 0, p_h, DD, nullptr, 1.f, 0);

        ln_kernel<<<MQ, 256>>>(p_h, p_norm, ln2g + l * DD, ln2b + l * DD);
        gemm(p_norm, f1w_l, p_ff, MQ, DFF, DD, DFF, 1,
             1, 0, 0, 1, 0, 0, 1, 0, 0, nullptr, 0, f1b_l, 1.f, 1);
        gemm(p_ff, f2w_l, p_h, MQ, DD, DFF, DD, 1,
             1, 0, 0, 1, 0, 0, 1, 0, 0, p_h, DD, f2b_l, 1.f, 0);
    }

    gemm(p_h, headw, out, MQ, NV, DD, NV, 1,
         1, 0, 0, 1, 0, 0, 1, 0, 0, nullptr, 0, headb, 1.f, 0);
}

// round 5
// speedup vs baseline: 3.0106x; 1.1194x over previous
#include <cuda_runtime.h>
#include <math.h>
#include <stdint.h>

#define BB   4
#define QQ   512
#define KKT  1024
#define DD   512
#define HH   8
#define DH   64
#define DFF  2048
#define NL   12
#define NV   332
#define MEML 512
#define UW   128
#define RKP  (KKT + UW)

// ---------------- scratch ----------------
__device__ float g_h[BB*QQ*DD];
__device__ float g_norm[BB*QQ*DD];
__device__ float g_wh[BB*QQ*3*DD];
__device__ float g_whmem[3*DD];
__device__ float g_posemb[KKT*DD];
__device__ float g_rk[KKT*DD];
__device__ float g_rkt[HH*RKP*DH];       // rk, [h][u][d], zero-padded
__device__ float g_vt[BB*HH*DH*QQ];      // V live rows, [bh][d][jq]
__device__ float g_c0[BB*HH*QQ];         // (q_i + rwb) . k_mem
__device__ float g_bwl[BB*HH*QQ];        // rwb . k_j (live rows)
__device__ float g_br[HH*RKP];           // rrb . rk_u (zero-padded)
__device__ float g_attn[BB*QQ*DD];
__device__ float g_ff[BB*QQ*DFF];
__device__ float g_gath[BB*QQ*DD];

__device__ __forceinline__ float to_tf32(float x) {
    uint32_t u;
    asm("cvt.rna.tf32.f32 %0, %1;" : "=r"(u) : "f"(x));
    return __uint_as_float(u);
}
__device__ __forceinline__ uint32_t to_tf32u(float x) {
    uint32_t u;
    asm("cvt.rna.tf32.f32 %0, %1;" : "=r"(u) : "f"(x));
    return u;
}

#define MMA_TF32(acc, a0,a1,a2,a3, b0,b1) \
    asm volatile("mma.sync.aligned.m16n8k8.row.col.f32.tf32.tf32.f32 " \
                 "{%0,%1,%2,%3}, {%4,%5,%6,%7}, {%8,%9}, {%0,%1,%2,%3};" \
                 : "+f"(acc[0]), "+f"(acc[1]), "+f"(acc[2]), "+f"(acc[3]) \
                 : "r"(a0), "r"(a1), "r"(a2), "r"(a3), "r"(b0), "r"(b1))

// ---------------- 128x128 tf32 tensor-core GEMM (unchanged) ----------------
#define BM 128
#define BN 128
#define LDS_K 20

__global__ __launch_bounds__(256, 2)
void gemm128(const float* __restrict__ A, const float* __restrict__ B,
             float* __restrict__ C,
             int M, int N, int Kd, int ldc,
             int zdA, long long hA, long long lA,
             int zdB, long long hB, long long lB,
             int zdC, long long hC, long long lC,
             const float* __restrict__ addsrc, int ldadd,
             const float* __restrict__ bias,
             float alpha, int relu)
{
    __shared__ float As[2][BM][LDS_K];
    __shared__ float Bs[2][BN][LDS_K];

    int z = blockIdx.z;
    A += (long long)(z / zdA) * hA + (long long)(z % zdA) * lA;
    B += (long long)(z / zdB) * hB + (long long)(z % zdB) * lB;
    C += (long long)(z / zdC) * hC + (long long)(z % zdC) * lC;

    int bm = blockIdx.y * BM, bn = blockIdx.x * BN;
    int tid  = threadIdx.x;
    int lane = tid & 31, warp = tid >> 5;
    int g  = lane >> 2, t4 = lane & 3;
    int wm = (warp >> 1) * 32;
    int wn = (warp & 1) * 64;

    int lrow = tid >> 2;
    int lkq  = (tid & 3) * 4;

    float acc[2][8][4];
#pragma unroll
    for (int mt = 0; mt < 2; mt++)
#pragma unroll
        for (int nt = 0; nt < 8; nt++)
#pragma unroll
            for (int q = 0; q < 4; q++) acc[mt][nt][q] = 0.f;

    float4 pa[2], pb[2];

    auto ldgA = [&](int k0, int it) -> float4 {
        int gm = bm + lrow + it * 64;
        if (gm < M) return *(const float4*)&A[(long long)gm * Kd + k0 + lkq];
        return make_float4(0.f, 0.f, 0.f, 0.f);
    };
    auto ldgB = [&](int k0, int it) -> float4 {
        int gn = bn + lrow + it * 64;
        if (gn < N) return *(const float4*)&B[(long long)gn * Kd + k0 + lkq];
        return make_float4(0.f, 0.f, 0.f, 0.f);
    };
    auto stash = [&](int buf) {
#pragma unroll
        for (int it = 0; it < 2; it++) {
            int r = lrow + it * 64;
            float4 ta = make_float4(to_tf32(pa[it].x), to_tf32(pa[it].y),
                                    to_tf32(pa[it].z), to_tf32(pa[it].w));
            float4 tb = make_float4(to_tf32(pb[it].x), to_tf32(pb[it].y),
                                    to_tf32(pb[it].z), to_tf32(pb[it].w));
            *(float4*)&As[buf][r][lkq] = ta;
            *(float4*)&Bs[buf][r][lkq] = tb;
        }
    };

    int nk = Kd >> 4;
    pa[0] = ldgA(0, 0); pa[1] = ldgA(0, 1);
    pb[0] = ldgB(0, 0); pb[1] = ldgB(0, 1);
    stash(0);
    __syncthreads();

    int buf = 0;
    for (int t = 0; t < nk; t++) {
        int has_next = (t + 1 < nk);
        if (has_next) {
            int k0 = (t + 1) << 4;
            pa[0] = ldgA(k0, 0); pa[1] = ldgA(k0, 1);
            pb[0] = ldgB(k0, 0); pb[1] = ldgB(k0, 1);
        }
#pragma unroll
        for (int ks = 0; ks < 16; ks += 8) {
            uint32_t af[2][4];
#pragma unroll
            for (int mt = 0; mt < 2; mt++) {
                int m0 = wm + mt * 16 + g;
                af[mt][0] = __float_as_uint(As[buf][m0    ][ks + t4    ]);
                af[mt][1] = __float_as_uint(As[buf][m0 + 8][ks + t4    ]);
                af[mt][2] = __float_as_uint(As[buf][m0    ][ks + t4 + 4]);
                af[mt][3] = __float_as_uint(As[buf][m0 + 8][ks + t4 + 4]);
            }
#pragma unroll
            for (int nt = 0; nt < 8; nt++) {
                int n0 = wn + nt * 8 + g;
                uint32_t b0 = __float_as_uint(Bs[buf][n0][ks + t4    ]);
                uint32_t b1 = __float_as_uint(Bs[buf][n0][ks + t4 + 4]);
#pragma unroll
                for (int mt = 0; mt < 2; mt++)
                    MMA_TF32(acc[mt][nt], af[mt][0], af[mt][1], af[mt][2], af[mt][3], b0, b1);
            }
        }
        if (has_next) {
            stash(buf ^ 1);
            __syncthreads();
            buf ^= 1;
        }
    }

    auto emit = [&](int gm, int gn, float v) {
        if (gm < M && gn < N) {
            v *= alpha;
            if (bias) v += bias[gn];
            if (relu) v = fmaxf(v, 0.f);
            if (addsrc) v += addsrc[(long long)gm * ldadd + gn];
            C[(long long)gm * ldc + gn] = v;
        }
    };
#pragma unroll
    for (int mt = 0; mt < 2; mt++) {
        int r0 = bm + wm + mt * 16 + g;
#pragma unroll
        for (int nt = 0; nt < 8; nt++) {
            int c0 = bn + wn + nt * 8 + t4 * 2;
            emit(r0,     c0,     acc[mt][nt][0]);
            emit(r0,     c0 + 1, acc[mt][nt][1]);
            emit(r0 + 8, c0,     acc[mt][nt][2]);
            emit(r0 + 8, c0 + 1, acc[mt][nt][3]);
        }
    }
}

// ---------------- fused flash attention with rel_shift + zero-mems shortcut ----------------
#define SQS 68
#define STS 84

__global__ __launch_bounds__(128, 2)
void attn_kernel()
{
    extern __shared__ float sm[];
    float* sK  = sm;                   // 64 x SQS
    float* sV  = sK + 64 * SQS;        // Vt: [d][j], 64 x SQS
    float* sRK = sV + 64 * SQS;        // 128 x SQS ; rows 0..63 reused as P
    float* sT  = sRK + UW * SQS;       // 64 x STS (per-warp relative cols)
    float* sBW = sT + 64 * STS;        // 64
    float* sBR = sBW + 64;             // 128
    float* sC0 = sBR + 128;            // 64

    int it = blockIdx.x;               // 0..7
    int bh = blockIdx.y;               // 0..31
    int h = bh & 7, b = bh >> 3;
    int i0 = it * 64;
    int tid = threadIdx.x, lane = tid & 31, warp = tid >> 5;
    int g = lane >> 2, t4 = lane & 3;
    int wr = warp * 16;
    int nt0w = 6 - 2 * warp;           // T col tile offset: 8*nt0w = 48-wr

    const float* RKg = g_rkt + (long long)h * RKP * DH;
    const float* Vtg = g_vt + (long long)bh * DH * QQ;

    // Q fragments in registers (tf32)
    uint32_t afQ[8][4];
    {
        long long qb = (long long)(b * QQ + i0) * (3 * DD) + h * 64;
        const float* q0 = g_wh + qb + (long long)(wr + g) * (3 * DD);
        const float* q1 = g_wh + qb + (long long)(wr + g + 8) * (3 * DD);
#pragma unroll
        for (int ks = 0; ks < 8; ks++) {
            afQ[ks][0] = to_tf32u(q0[ks * 8 + t4]);
            afQ[ks][1] = to_tf32u(q1[ks * 8 + t4]);
            afQ[ks][2] = to_tf32u(q0[ks * 8 + t4 + 4]);
            afQ[ks][3] = to_tf32u(q1[ks * 8 + t4 + 4]);
        }
    }
    if (tid < 64) sC0[tid] = g_c0[bh * QQ + i0 + tid];

    float mrow[2] = {-1e30f, -1e30f};
    float lrow[2] = {0.f, 0.f};
    float msum[2] = {0.f, 0.f};
    float O[8][4];
#pragma unroll
    for (int nt = 0; nt < 8; nt++)
#pragma unroll
        for (int q = 0; q < 4; q++) O[nt][q] = 0.f;

    int njt = it + 9;
    for (int jt = 0; jt < njt; jt++) {
        int j0 = jt * 64;
        int mem = (jt < 8);
        int ub = j0 - i0 + 448;
        __syncthreads();
        // RK window load (always)
        {
            const float* rs = RKg + (long long)(ub + tid) * DH;
            float* rd = sRK + tid * SQS;
#pragma unroll
            for (int q = 0; q < 16; q++) {
                float4 v = *(const float4*)(rs + q * 4);
                rd[q*4+0] = to_tf32(v.x); rd[q*4+1] = to_tf32(v.y);
                rd[q*4+2] = to_tf32(v.z); rd[q*4+3] = to_tf32(v.w);
            }
        }
        if (!mem) {
            int r = tid >> 1, half = (tid & 1) * 32;
            const float* ksrc = g_wh + (long long)(b * QQ + j0 - MEML + r) * (3 * DD) + DD + h * 64 + half;
            float* kd = sK + r * SQS + half;
            const float* vsrc = Vtg + (long long)r * QQ + (j0 - MEML) + half;
            float* vd = sV + r * SQS + half;
#pragma unroll
            for (int q = 0; q < 8; q++) {
                float4 v = *(const float4*)(ksrc + q * 4);
                kd[q*4+0] = to_tf32(v.x); kd[q*4+1] = to_tf32(v.y);
                kd[q*4+2] = to_tf32(v.z); kd[q*4+3] = to_tf32(v.w);
                float4 w = *(const float4*)(vsrc + q * 4);
                vd[q*4+0] = to_tf32(w.x); vd[q*4+1] = to_tf32(w.y);
                vd[q*4+2] = to_tf32(w.z); vd[q*4+3] = to_tf32(w.w);
            }
            if (tid < 64) sBW[tid] = g_bwl[bh * QQ + (j0 - MEML) + tid];
        }
        sBR[tid] = g_br[h * RKP + ub + tid];
        __syncthreads();

        float ac[8][4];
        float tf[10][4];
#pragma unroll
        for (int nt = 0; nt < 8; nt++)
#pragma unroll
            for (int q = 0; q < 4; q++) ac[nt][q] = 0.f;
#pragma unroll
        for (int nt = 0; nt < 10; nt++)
#pragma unroll
            for (int q = 0; q < 4; q++) tf[nt][q] = 0.f;

#pragma unroll
        for (int ks = 0; ks < 8; ks++) {
            uint32_t a0 = afQ[ks][0], a1 = afQ[ks][1], a2 = afQ[ks][2], a3 = afQ[ks][3];
            if (!mem) {
#pragma unroll
                for (int nt = 0; nt < 8; nt++) {
                    uint32_t b0 = __float_as_uint(sK[(nt * 8 + g) * SQS + ks * 8 + t4    ]);
                    uint32_t b1 = __float_as_uint(sK[(nt * 8 + g) * SQS + ks * 8 + t4 + 4]);
                    MMA_TF32(ac[nt], a0, a1, a2, a3, b0, b1);
                }
            }
#pragma unroll
            for (int nt = 0; nt < 10; nt++) {
                int u = (nt0w + nt) * 8 + g;
                uint32_t b0 = __float_as_uint(sRK[u * SQS + ks * 8 + t4    ]);
                uint32_t b1 = __float_as_uint(sRK[u * SQS + ks * 8 + t4 + 4]);
                MMA_TF32(tf[nt], a0, a1, a2, a3, b0, b1);
            }
        }
        __syncthreads();   // all sRK reads done (P overwrite below is cross-warp safe)

        // T accumulators -> SMEM (per-warp relative cols)
#pragma unroll
        for (int nt = 0; nt < 10; nt++) {
            int cr = nt * 8 + t4 * 2;
            sT[(wr + g    ) * STS + cr    ] = tf[nt][0];
            sT[(wr + g    ) * STS + cr + 1] = tf[nt][1];
            sT[(wr + g + 8) * STS + cr    ] = tf[nt][2];
            sT[(wr + g + 8) * STS + cr + 1] = tf[nt][3];
        }
        __syncwarp();

        int last = (jt == it + 8);
        float mt2[2] = {-1e30f, -1e30f};
#pragma unroll
        for (int nt = 0; nt < 8; nt++) {
            int jl0 = nt * 8 + t4 * 2;
#pragma unroll
            for (int r2 = 0; r2 < 2; r2++) {
                int il = wr + g + r2 * 8;
#pragma unroll
                for (int cc = 0; cc < 2; cc++) {
                    int jl = jl0 + cc;
                    int crel = jl - g - r2 * 8 + 15;      // relative T col
                    float base = mem ? sC0[il] : (ac[nt][r2*2+cc] + sBW[jl]);
                    float s = (base + sT[il * STS + crel] + sBR[jl - il + 63]) * 0.125f;
                    if (last && jl > il) s = -1e30f;
                    ac[nt][r2*2+cc] = s;
                    mt2[r2] = fmaxf(mt2[r2], s);
                }
            }
        }
#pragma unroll
        for (int r2 = 0; r2 < 2; r2++) {
            mt2[r2] = fmaxf(mt2[r2], __shfl_xor_sync(0xffffffffu, mt2[r2], 1));
            mt2[r2] = fmaxf(mt2[r2], __shfl_xor_sync(0xffffffffu, mt2[r2], 2));
        }
        float corr[2], ls[2] = {0.f, 0.f};
#pragma unroll
        for (int r2 = 0; r2 < 2; r2++) {
            float mnew = fmaxf(mrow[r2], mt2[r2]);
            corr[r2] = __expf(mrow[r2] - mnew);
            mrow[r2] = mnew;
        }
#pragma unroll
        for (int nt = 0; nt < 8; nt++)
#pragma unroll
            for (int r2 = 0; r2 < 2; r2++)
#pragma unroll
                for (int cc = 0; cc < 2; cc++) {
                    float e = __expf(ac[nt][r2*2+cc] - mrow[r2]);
                    ac[nt][r2*2+cc] = e;
                    ls[r2] += e;
                }
#pragma unroll
        for (int r2 = 0; r2 < 2; r2++) {
            ls[r2] += __shfl_xor_sync(0xffffffffu, ls[r2], 1);
            ls[r2] += __shfl_xor_sync(0xffffffffu, ls[r2], 2);
            lrow[r2] = lrow[r2] * corr[r2] + ls[r2];
            msum[r2] *= corr[r2];
            if (mem) msum[r2] += ls[r2];
        }
#pragma unroll
        for (int nt = 0; nt < 8; nt++)
#pragma unroll
            for (int q = 0; q < 4; q++) O[nt][q] *= corr[q >> 1];

        if (!mem) {
            // P (tf32) -> sRK rows 0..63
#pragma unroll
            for (int nt = 0; nt < 8; nt++) {
                int c = nt * 8 + t4 * 2;
                sRK[(wr + g    ) * SQS + c    ] = to_tf32(ac[nt][0]);
                sRK[(wr + g    ) * SQS + c + 1] = to_tf32(ac[nt][1]);
                sRK[(wr + g + 8) * SQS + c    ] = to_tf32(ac[nt][2]);
                sRK[(wr + g + 8) * SQS + c + 1] = to_tf32(ac[nt][3]);
            }
            __syncwarp();
#pragma unroll
            for (int ks = 0; ks < 8; ks++) {
                uint32_t a0 = __float_as_uint(sRK[(wr + g    ) * SQS + ks * 8 + t4    ]);
                uint32_t a1 = __float_as_uint(sRK[(wr + g + 8) * SQS + ks * 8 + t4    ]);
                uint32_t a2 = __float_as_uint(sRK[(wr + g    ) * SQS + ks * 8 + t4 + 4]);
                uint32_t a3 = __float_as_uint(sRK[(wr + g + 8) * SQS + ks * 8 + t4 + 4]);
#pragma unroll
                for (int nt = 0; nt < 8; nt++) {
                    uint32_t b0 = __float_as_uint(sV[(nt * 8 + g) * SQS + ks * 8 + t4    ]);
                    uint32_t b1 = __float_as_uint(sV[(nt * 8 + g) * SQS + ks * 8 + t4 + 4]);
                    MMA_TF32(O[nt], a0, a1, a2, a3, b0, b1);
                }
            }
        }
    }

    // epilogue: add mem-region rank-1 term, normalize, scatter
    float inv0 = 1.f / lrow[0], inv1 = 1.f / lrow[1];
    const float* vm = g_whmem + 2 * DD + h * 64;
    long long r0 = (long long)(b * QQ + i0 + wr + g) * DD + h * 64;
    long long r1 = (long long)(b * QQ + i0 + wr + g + 8) * DD + h * 64;
#pragma unroll
    for (int nt = 0; nt < 8; nt++) {
        int c = nt * 8 + t4 * 2;
        float v0 = vm[c], v1 = vm[c + 1];
        g_attn[r0 + c]     = (O[nt][0] + msum[0] * v0) * inv0;
        g_attn[r0 + c + 1] = (O[nt][1] + msum[0] * v1) * inv0;
        g_attn[r1 + c]     = (O[nt][2] + msum[1] * v0) * inv1;
        g_attn[r1 + c + 1] = (O[nt][3] + msum[1] * v1) * inv1;
    }
}

// ---------------- layernorm ----------------
__global__ void ln_kernel(const float* __restrict__ x, float* __restrict__ y,
                          const float* __restrict__ g, const float* __restrict__ b)
{
    int row = blockIdx.x;
    const float* xr = x + (long long)row * DD;
    float* yr = y + (long long)row * DD;
    int tid = threadIdx.x;  // 256
    float v0 = xr[tid], v1 = xr[tid + 256];
    float s = v0 + v1, s2 = v0 * v0 + v1 * v1;
    __shared__ float sh[16];
#pragma unroll
    for (int o = 16; o > 0; o >>= 1) {
        s  += __shfl_xor_sync(0xffffffffu, s,  o);
        s2 += __shfl_xor_sync(0xffffffffu, s2, o);
    }
    if ((tid & 31) == 0) { sh[tid >> 5] = s; sh[(tid >> 5) + 8] = s2; }
    __syncthreads();
    __shared__ float mu_s, rs_s;
    if (tid == 0) {
        float S = 0.f, S2 = 0.f;
        for (int w = 0; w < 8; w++) { S += sh[w]; S2 += sh[w + 8]; }
        float mu = S / DD;
        float var = S2 / DD - mu * mu;
        mu_s = mu;
        rs_s = rsqrtf(var + 1e-3f);
    }
    __syncthreads();
    float mu = mu_s, rs = rs_s;
    yr[tid]       = (v0 - mu) * rs * g[tid]       + b[tid];
    yr[tid + 256] = (v1 - mu) * rs * g[tid + 256] + b[tid + 256];
}

__global__ void whmem_kernel(const float* __restrict__ qkvw, const float* __restrict__ lnb)
{
    int n = blockIdx.x * blockDim.x + threadIdx.x;
    if (n >= 3 * DD) return;
    const float* wr = qkvw + (long long)n * DD;
    float s = 0.f;
    for (int c = 0; c < DD; c++) s += lnb[c] * wr[c];
    g_whmem[n] = s;
}

__global__ void posemb_kernel()
{
    int idx = blockIdx.x * blockDim.x + threadIdx.x;
    if (idx >= KKT * DD) return;
    int p = idx / DD, c = idx % DD;
    float pos = (float)(KKT - 1 - p);
    int k = (c < 256) ? c : (c - 256);
    float invf = powf(10000.0f, -((float)(2 * k)) / 512.0f);
    float a = pos * invf;
    g_posemb[idx] = (c < 256) ? sinf(a) : cosf(a);
}

__global__ void gather_kernel(const int* __restrict__ ids, const float* __restrict__ emb)
{
    int idx = blockIdx.x * blockDim.x + threadIdx.x;
    if (idx >= BB * QQ * DD) return;
    int m = idx / DD, c = idx % DD;
    g_gath[idx] = emb[(long long)ids[m] * DD + c];
}

// V live rows transpose: g_vt[bh][d][jq] = V[b, jq, h*64+d]
__global__ void packvt_kernel()
{
    int idx = blockIdx.x * blockDim.x + threadIdx.x;
    if (idx >= BB * HH * DH * QQ) return;
    int jq = idx & 511;
    int d  = (idx >> 9) & 63;
    int bh = idx >> 15;
    int b = bh >> 3, h = bh & 7;
    g_vt[idx] = g_wh[(long long)(b * QQ + jq) * (3 * DD) + 2 * DD + h * 64 + d];
}

__global__ void packrk_kernel()
{
    int idx = blockIdx.x * blockDim.x + threadIdx.x;
    if (idx >= HH * RKP * DH) return;
    int d = idx & 63;
    int p = (idx >> 6) % RKP;
    int h = idx / (RKP * DH);
    g_rkt[idx] = (p < KKT) ? g_rk[(long long)p * DD + h * 64 + d] : 0.f;
}

// c0[bh][i] = (q_i + rwb_h) . k_mem ;  bwl[bh][jq] = rwb_h . k_jq
__global__ void c0bw_kernel(const float* __restrict__ rwb)
{
    int row = blockIdx.x;
    int t = threadIdx.x;               // 64
    int kind = row >> 14;
    int r = row & 16383;
    int bh = r >> 9, iq = r & 511;
    int h = bh & 7, b = bh >> 3;
    long long base = (long long)(b * QQ + iq) * (3 * DD) + h * 64;
    float v;
    if (kind == 0) {
        v = (g_wh[base + t] + rwb[h * 64 + t]) * g_whmem[DD + h * 64 + t];
    } else {
        v = rwb[h * 64 + t] * g_wh[base + DD + t];
    }
#pragma unroll
    for (int o = 16; o > 0; o >>= 1) v += __shfl_xor_sync(0xffffffffu, v, o);
    __shared__ float sh[2];
    if ((t & 31) == 0) sh[t >> 5] = v;
    __syncthreads();
    if (t == 0) {
        float s = sh[0] + sh[1];
        if (kind == 0) g_c0[r] = s; else g_bwl[r] = s;
    }
}

// br[h][u] = rrb_h . rk[h][u] (0 beyond 1023)
__global__ void br_kernel(const float* __restrict__ rrb)
{
    int idx = blockIdx.x * blockDim.x + threadIdx.x;
    if (idx >= HH * RKP) return;
    int h = idx / RKP, u = idx % RKP;
    float s = 0.f;
    if (u < KKT) {
        const float* rr = g_rk + (long long)u * DD + h * 64;
        const float* w = rrb + h * DH;
#pragma unroll
        for (int d = 0; d < DH; d++) s += w[d] * rr[d];
    }
    g_br[idx] = s;
}

// ---------------- host ----------------
static void gemm(const float* A, const float* B, float* C,
                 int M, int N, int K, int ldc, int nz,
                 int zdA, long long hA, long long lA,
                 int zdB, long long hB, long long lB,
                 int zdC, long long hC, long long lC,
                 const float* add, int ldadd, const float* bias,
                 float alpha, int relu)
{
    dim3 grid((N + BN - 1) / BN, (M + BM - 1) / BM, nz);
    gemm128<<<grid, 256>>>(A, B, C, M, N, K, ldc,
                           zdA, hA, lA, zdB, hB, lB, zdC, hC, lC,
                           add, ldadd, bias, alpha, relu);
}

extern "C" void kernel_launch(void* const* d_in, const int* in_sizes, int n_in,
                              void* d_out, int out_size)
{
    const int*   ids      = (const int*)d_in[0];
    const float* emb      = (const float*)d_in[1];
    const float* emb_proj = (const float*)d_in[2];
    const float* rwb      = (const float*)d_in[3];
    const float* rrb      = (const float*)d_in[4];
    const float* qkv_w    = (const float*)d_in[5];
    const float* o_w      = (const float*)d_in[6];
    const float* rnet_w   = (const float*)d_in[7];
    const float* ln1g     = (const float*)d_in[8];
    const float* ln1b     = (const float*)d_in[9];
    const float* ff1w     = (const float*)d_in[10];
    const float* ff1b     = (const float*)d_in[11];
    const float* ff2w     = (const float*)d_in[12];
    const float* ff2b     = (const float*)d_in[13];
    const float* ln2g     = (const float*)d_in[14];
    const float* ln2b     = (const float*)d_in[15];
    const float* headw    = (const float*)d_in[16];
    const float* headb    = (const float*)d_in[17];
    float* out = (float*)d_out;

    float *p_h, *p_norm, *p_wh, *p_posemb, *p_rk, *p_attn, *p_ff, *p_gath;
    void* tmp;
#define SYM(v, s) cudaGetSymbolAddress(&tmp, s); v = (float*)tmp;
    SYM(p_h, g_h) SYM(p_norm, g_norm) SYM(p_wh, g_wh) SYM(p_posemb, g_posemb)
    SYM(p_rk, g_rk) SYM(p_attn, g_attn) SYM(p_ff, g_ff) SYM(p_gath, g_gath)
#undef SYM

    const int ATTN_SMEM = (2 * 64 * SQS + UW * SQS + 64 * STS + 64 + 128 + 64) * 4;
    cudaFuncSetAttribute(attn_kernel, cudaFuncAttributeMaxDynamicSharedMemorySize, ATTN_SMEM);

    const int MQ = BB * QQ;

    gather_kernel<<<(MQ * DD + 255) / 256, 256>>>(ids, emb);
    posemb_kernel<<<(KKT * DD + 255) / 256, 256>>>();
    gemm(p_gath, emb_proj, p_h, MQ, DD, DD, DD, 1,
         1, 0, 0, 1, 0, 0, 1, 0, 0, nullptr, 0, nullptr, sqrtf((float)DD), 0);

    for (int l = 0; l < NL; l++) {
        const float* qkvw_l = qkv_w + (long long)l * 3 * DD * DD;
        const float* ow_l   = o_w   + (long long)l * DD * DD;
        const float* rnw_l  = rnet_w+ (long long)l * DD * DD;
        const float* f1w_l  = ff1w  + (long long)l * DFF * DD;
        const float* f1b_l  = ff1b  + (long long)l * DFF;
        const float* f2w_l  = ff2w  + (long long)l * DD * DFF;
        const float* f2b_l  = ff2b  + (long long)l * DD;

        ln_kernel<<<MQ, 256>>>(p_h, p_norm, ln1g + l * DD, ln1b + l * DD);
        whmem_kernel<<<12, 128>>>(qkvw_l, ln1b + l * DD);
        gemm(p_norm, qkvw_l, p_wh, MQ, 3 * DD, DD, 3 * DD, 1,
             1, 0, 0, 1, 0, 0, 1, 0, 0, nullptr, 0, nullptr, 1.f, 0);

        gemm(p_posemb, rnw_l, p_rk, KKT, DD, DD, DD, 1,
             1, 0, 0, 1, 0, 0, 1, 0, 0, nullptr, 0, nullptr, 1.f, 0);

        packrk_kernel<<<(HH * RKP * DH + 255) / 256, 256>>>();
        packvt_kernel<<<(BB * HH * DH * QQ + 255) / 256, 256>>>();
        c0bw_kernel<<<2 * BB * HH * QQ, 64>>>(rwb);
        br_kernel<<<(HH * RKP + 255) / 256, 256>>>(rrb);

        attn_kernel<<<dim3(QQ / 64, BB * HH), 128, ATTN_SMEM>>>();

        gemm(p_attn, ow_l, p_h, MQ, DD, DD, DD, 1,
             1, 0, 0, 1, 0, 0, 1, 0, 0, p_h, DD, nullptr, 1.f, 0);

        ln_kernel<<<MQ, 256>>>(p_h, p_norm, ln2g + l * DD, ln2b + l * DD);
        gemm(p_norm, f1w_l, p_ff, MQ, DFF, DD, DFF, 1,
             1, 0, 0, 1, 0, 0, 1, 0, 0, nullptr, 0, f1b_l, 1.f, 1);
        gemm(p_ff, f2w_l, p_h, MQ, DD, DFF, DD, 1,
             1, 0, 0, 1, 0, 0, 1, 0, 0, p_h, DD, f2b_l, 1.f, 0);
    }

    gemm(p_h, headw, out, MQ, NV, DD, NV, 1,
         1, 0, 0, 1, 0, 0, 1, 0, 0, nullptr, 0, headb, 1.f, 0);
}